// round 1
// baseline (speedup 1.0000x reference)
#include <cuda_runtime.h>
#include <cuda_bf16.h>
#include <math.h>

#define BATCH   2
#define S_LEN   2048
#define D_MODEL 2048
#define NHEADS  32
#define NKVH    8
#define HDIM    64
#define GSIZE   (NHEADS / NKVH)      // 4
#define KVD     (NKVH * HDIM)        // 512
#define MROWS   (BATCH * S_LEN)      // 4096

// ---------------- scratch (device globals; no cudaMalloc allowed) ----------
__device__ float g_q  [BATCH * S_LEN * D_MODEL];   // 33.5 MB
__device__ float g_k  [BATCH * S_LEN * KVD];       //  8.4 MB
__device__ float g_v  [BATCH * S_LEN * KVD];       //  8.4 MB
__device__ float g_ctx[BATCH * S_LEN * D_MODEL];   // 33.5 MB

// ---------------- 128x128x8 fp32 SGEMM, 256 threads, 8x8 microtile ---------
__global__ __launch_bounds__(256)
void sgemm128(const float* __restrict__ A, const float* __restrict__ B,
              float* __restrict__ C, int M, int N, int K)
{
    __shared__ float As[8][128];
    __shared__ float Bs[8][128];

    const int tid = threadIdx.x;
    const int bm  = blockIdx.y * 128;
    const int bn  = blockIdx.x * 128;
    const int tx  = tid & 15;   // 0..15
    const int ty  = tid >> 4;   // 0..15

    float acc[8][8];
    #pragma unroll
    for (int i = 0; i < 8; i++)
        #pragma unroll
        for (int j = 0; j < 8; j++) acc[i][j] = 0.f;

    // A-tile load: 128 rows x 8 cols = 256 float4; one per thread
    const int a_row = tid >> 1;          // 0..127
    const int a_col = (tid & 1) * 4;     // 0 or 4
    // B-tile load: 8 rows x 128 cols = 256 float4
    const int b_row = tid >> 5;          // 0..7
    const int b_col = (tid & 31) * 4;    // 0..124

    const float* Ablk = A + (size_t)(bm) * K;
    const float* Bblk = B + bn;

    for (int k0 = 0; k0 < K; k0 += 8) {
        float4 av = *(const float4*)(Ablk + (size_t)a_row * K + k0 + a_col);
        As[a_col + 0][a_row] = av.x;
        As[a_col + 1][a_row] = av.y;
        As[a_col + 2][a_row] = av.z;
        As[a_col + 3][a_row] = av.w;
        float4 bv = *(const float4*)(Bblk + (size_t)(k0 + b_row) * N + b_col);
        *(float4*)(&Bs[b_row][b_col]) = bv;
        __syncthreads();

        #pragma unroll
        for (int kk = 0; kk < 8; kk++) {
            float ra[8], rb[8];
            float4 t0 = *(const float4*)(&As[kk][ty * 8 + 0]);
            float4 t1 = *(const float4*)(&As[kk][ty * 8 + 4]);
            ra[0]=t0.x; ra[1]=t0.y; ra[2]=t0.z; ra[3]=t0.w;
            ra[4]=t1.x; ra[5]=t1.y; ra[6]=t1.z; ra[7]=t1.w;
            float4 u0 = *(const float4*)(&Bs[kk][tx * 8 + 0]);
            float4 u1 = *(const float4*)(&Bs[kk][tx * 8 + 4]);
            rb[0]=u0.x; rb[1]=u0.y; rb[2]=u0.z; rb[3]=u0.w;
            rb[4]=u1.x; rb[5]=u1.y; rb[6]=u1.z; rb[7]=u1.w;
            #pragma unroll
            for (int i = 0; i < 8; i++)
                #pragma unroll
                for (int j = 0; j < 8; j++)
                    acc[i][j] += ra[i] * rb[j];
        }
        __syncthreads();
    }

    #pragma unroll
    for (int i = 0; i < 8; i++) {
        float* crow = C + (size_t)(bm + ty * 8 + i) * N + bn + tx * 8;
        float4 w0, w1;
        w0.x = acc[i][0]; w0.y = acc[i][1]; w0.z = acc[i][2]; w0.w = acc[i][3];
        w1.x = acc[i][4]; w1.y = acc[i][5]; w1.z = acc[i][6]; w1.w = acc[i][7];
        *(float4*)(crow + 0) = w0;
        *(float4*)(crow + 4) = w1;
    }
}

// ---------------- RoPE (in-place) -------------------------------------------
// buf viewed as [B*S, heads, 64]; pairs (j, j+32) rotated by angle s*inv_freq[j]
__global__ void rope_kernel(float* __restrict__ buf, int heads, int total_pairs)
{
    int idx = blockIdx.x * blockDim.x + threadIdx.x;
    if (idx >= total_pairs) return;
    int j   = idx & 31;
    int t   = idx >> 5;
    int h   = t % heads;
    int row = t / heads;          // b*S + s
    int s   = row & (S_LEN - 1);

    float inv = (float)exp(-(double)j * (log(10000.0) / 32.0));
    float ang = (float)s * inv;
    float c, sn;
    sincosf(ang, &sn, &c);

    float* p = buf + (size_t)row * heads * HDIM + h * HDIM + j;
    float x1 = p[0];
    float x2 = p[32];
    p[0]  = x1 * c - x2 * sn;
    p[32] = x2 * c + x1 * sn;
}

// ---------------- causal GQA flash attention ---------------------------------
// grid: (S/64, NH, B); block: 64 threads, one query row each.
// q: [B*S, NH*HD]  k,v: [B*S, NKV*HD]  ctx: [B*S, NH*HD]
__global__ __launch_bounds__(64)
void attn_kernel(const float* __restrict__ q, const float* __restrict__ k,
                 const float* __restrict__ v, float* __restrict__ ctx)
{
    __shared__ float k_s[32][64];
    __shared__ float v_s[32][64];
    __shared__ float s_s[64][33];   // pad to 33 -> conflict-free row access

    const int qb  = blockIdx.x;
    const int h   = blockIdx.y;
    const int b   = blockIdx.z;
    const int kvh = h / GSIZE;
    const int tid = threadIdx.x;
    const int qg  = qb * 64 + tid;          // global query index in sequence

    const float* qrow = q + ((size_t)b * S_LEN + qg) * D_MODEL + h * HDIM;
    float qreg[64];
    #pragma unroll
    for (int d = 0; d < 64; d += 4) {
        float4 t = *(const float4*)(qrow + d);
        qreg[d+0]=t.x; qreg[d+1]=t.y; qreg[d+2]=t.z; qreg[d+3]=t.w;
    }

    float m = -1e30f, l = 0.f;
    float acc[64];
    #pragma unroll
    for (int d = 0; d < 64; d++) acc[d] = 0.f;

    const float scale = 0.125f;   // 1/sqrt(64)
    const int nkb = 2 * qb + 2;   // causal: k blocks 0 .. 2*qb+1 (32-wide)
    const float* kbase = k + (size_t)b * S_LEN * KVD + kvh * HDIM;
    const float* vbase = v + (size_t)b * S_LEN * KVD + kvh * HDIM;

    for (int kb = 0; kb < nkb; kb++) {
        __syncthreads();   // previous-iteration smem reads finished
        // cooperative tile load: 32 rows x 16 float4 = 512 float4 / 64 thr = 8 each
        #pragma unroll
        for (int r = 0; r < 8; r++) {
            int idx = tid + 64 * r;       // 0..511
            int row = idx >> 4;
            int c4  = (idx & 15) * 4;
            size_t goff = (size_t)(kb * 32 + row) * KVD + c4;
            *(float4*)(&k_s[row][c4]) = *(const float4*)(kbase + goff);
            *(float4*)(&v_s[row][c4]) = *(const float4*)(vbase + goff);
        }
        __syncthreads();

        // scores for my row
        float mb = -1e30f;
        for (int ki = 0; ki < 32; ki++) {
            float sum = 0.f;
            #pragma unroll
            for (int d = 0; d < 64; d++) sum += qreg[d] * k_s[ki][d];
            int kg = kb * 32 + ki;
            float sv = (kg <= qg) ? sum * scale : -1e30f;
            s_s[tid][ki] = sv;
            mb = fmaxf(mb, sv);
        }

        float mnew = fmaxf(m, mb);
        float corr = __expf(m - mnew);
        l *= corr;
        #pragma unroll
        for (int d = 0; d < 64; d++) acc[d] *= corr;

        for (int ki = 0; ki < 32; ki++) {
            float p = __expf(s_s[tid][ki] - mnew);
            l += p;
            #pragma unroll
            for (int d = 0; d < 64; d++) acc[d] += p * v_s[ki][d];
        }
        m = mnew;
    }

    float invl = 1.f / l;
    float* out = ctx + ((size_t)b * S_LEN + qg) * D_MODEL + h * HDIM;
    #pragma unroll
    for (int d = 0; d < 64; d += 4) {
        float4 t;
        t.x = acc[d+0]*invl; t.y = acc[d+1]*invl;
        t.z = acc[d+2]*invl; t.w = acc[d+3]*invl;
        *(float4*)(out + d) = t;
    }
}

// ---------------- host launch -------------------------------------------------
extern "C" void kernel_launch(void* const* d_in, const int* in_sizes, int n_in,
                              void* d_out, int out_size)
{
    const float* x  = (const float*)d_in[0];
    const float* Wq = (const float*)d_in[1];
    const float* Wk = (const float*)d_in[2];
    const float* Wv = (const float*)d_in[3];
    const float* Wo = (const float*)d_in[4];
    float* out = (float*)d_out;

    float *q, *k, *v, *ctx;
    cudaGetSymbolAddress((void**)&q,   g_q);
    cudaGetSymbolAddress((void**)&k,   g_k);
    cudaGetSymbolAddress((void**)&v,   g_v);
    cudaGetSymbolAddress((void**)&ctx, g_ctx);

    // QKV projections
    sgemm128<<<dim3(D_MODEL/128, MROWS/128), 256>>>(x, Wq, q, MROWS, D_MODEL, D_MODEL);
    sgemm128<<<dim3(KVD/128,     MROWS/128), 256>>>(x, Wk, k, MROWS, KVD,     D_MODEL);
    sgemm128<<<dim3(KVD/128,     MROWS/128), 256>>>(x, Wv, v, MROWS, KVD,     D_MODEL);

    // RoPE on q and k
    {
        int pairs_q = MROWS * NHEADS * 32;
        int pairs_k = MROWS * NKVH  * 32;
        rope_kernel<<<(pairs_q + 255)/256, 256>>>(q, NHEADS, pairs_q);
        rope_kernel<<<(pairs_k + 255)/256, 256>>>(k, NKVH,  pairs_k);
    }

    // attention
    attn_kernel<<<dim3(S_LEN/64, NHEADS, BATCH), 64>>>(q, k, v, ctx);

    // output projection
    sgemm128<<<dim3(D_MODEL/128, MROWS/128), 256>>>(ctx, Wo, out, MROWS, D_MODEL, D_MODEL);
}

// round 3
// speedup vs baseline: 1.7919x; 1.7919x over previous
#include <cuda_runtime.h>
#include <cuda_bf16.h>
#include <math.h>
#include <cstdint>

#define BATCH   2
#define S_LEN   2048
#define D_MODEL 2048
#define NHEADS  32
#define NKVH    8
#define HDIM    64
#define GSIZE   (NHEADS / NKVH)
#define KVD     (NKVH * HDIM)        // 512
#define MROWS   (BATCH * S_LEN)      // 4096
#define KDIM    2048
#define KEFF    (3 * KDIM)           // 6144 stacked K

// ---------------- scratch (device globals) ----------------------------------
__device__ float g_q  [MROWS * D_MODEL];
__device__ float g_k  [MROWS * KVD];
__device__ float g_v  [MROWS * KVD];
__device__ float g_ctx[MROWS * D_MODEL];
__device__ __nv_bfloat16 g_ahat[(size_t)MROWS  * KEFF];   // x-hat, later ctx-hat
__device__ __nv_bfloat16 g_wq [(size_t)D_MODEL * KEFF];
__device__ __nv_bfloat16 g_wk [(size_t)KVD     * KEFF];
__device__ __nv_bfloat16 g_wv [(size_t)KVD     * KEFF];
__device__ __nv_bfloat16 g_wo [(size_t)D_MODEL * KEFF];
__device__ float g_cos[S_LEN * 32];
__device__ float g_sin[S_LEN * 32];

// ---------------- helpers ------------------------------------------------
__device__ __forceinline__ uint32_t smem_u32(const void* p) {
    uint32_t a;
    asm("{ .reg .u64 t; cvta.to.shared.u64 t, %1; cvt.u32.u64 %0, t; }"
        : "=r"(a) : "l"(p));
    return a;
}

__device__ __forceinline__ void ldsm4(uint32_t& r0, uint32_t& r1, uint32_t& r2,
                                      uint32_t& r3, uint32_t addr) {
    asm volatile("ldmatrix.sync.aligned.m8n8.x4.shared.b16 {%0,%1,%2,%3}, [%4];"
                 : "=r"(r0), "=r"(r1), "=r"(r2), "=r"(r3) : "r"(addr));
}

__device__ __forceinline__ void mma16816(float* d, const uint32_t* a, const uint32_t* b) {
    asm volatile(
        "mma.sync.aligned.m16n8k16.row.col.f32.bf16.bf16.f32 "
        "{%0,%1,%2,%3}, {%4,%5,%6,%7}, {%8,%9}, {%0,%1,%2,%3};"
        : "+f"(d[0]), "+f"(d[1]), "+f"(d[2]), "+f"(d[3])
        : "r"(a[0]), "r"(a[1]), "r"(a[2]), "r"(a[3]), "r"(b[0]), "r"(b[1]));
}

// ---------------- conversion kernels -----------------------------------------
// fp32 [rows][2048] -> bf16 [rows][6144] stacked (hi | lo | hi)
__global__ void conv_split(const float* __restrict__ in, __nv_bfloat16* __restrict__ out,
                           int total)
{
    int i = blockIdx.x * blockDim.x + threadIdx.x;
    if (i >= total) return;
    int row = i / KDIM, col = i - row * KDIM;
    float v = in[i];
    __nv_bfloat16 hi = __float2bfloat16(v);
    __nv_bfloat16 lo = __float2bfloat16(v - __bfloat162float(hi));
    size_t base = (size_t)row * KEFF + col;
    out[base]            = hi;
    out[base + KDIM]     = lo;
    out[base + 2 * KDIM] = hi;
}

// W fp32 [2048][N] -> bf16 [N][6144] transposed stacked (hi | hi | lo)
__global__ void conv_wt(const float* __restrict__ W, __nv_bfloat16* __restrict__ out, int N)
{
    __shared__ float tile[32][33];
    int k0 = blockIdx.y * 32, n0 = blockIdx.x * 32;
    int tx = threadIdx.x, ty = threadIdx.y;
    tile[ty][tx] = W[(size_t)(k0 + ty) * N + n0 + tx];
    __syncthreads();
    float v = tile[tx][ty];   // = W[k0+tx][n0+ty]
    __nv_bfloat16 hi = __float2bfloat16(v);
    __nv_bfloat16 lo = __float2bfloat16(v - __bfloat162float(hi));
    size_t base = (size_t)(n0 + ty) * KEFF + k0 + tx;
    out[base]            = hi;
    out[base + KDIM]     = hi;
    out[base + 2 * KDIM] = lo;
}

// ---------------- HMMA bf16 GEMM: C[M,N] = Ahat[M,6144] @ Bhat[N,6144]^T ------
// block 128x128, 8 warps (4M x 2N), warp tile 32x64, KC=32 double-buffered.
#define BM 128
#define BN 128
#define KC 32
#define NCHUNK (KEFF / KC)     // 192
#define RSTRIDE 40             // bf16 elems per smem row (80 B)

__global__ __launch_bounds__(256)
void gemm_hmma(const __nv_bfloat16* __restrict__ A, const __nv_bfloat16* __restrict__ B,
               float* __restrict__ C, int N)
{
    __shared__ __nv_bfloat16 As[2][BM * RSTRIDE];
    __shared__ __nv_bfloat16 Bs[2][BN * RSTRIDE];

    const int tid  = threadIdx.x;
    const int wid  = tid >> 5;
    const int lane = tid & 31;
    const int bm   = blockIdx.y * BM;
    const int bn   = blockIdx.x * BN;
    const int wm   = (wid & 3) * 32;     // warp M offset
    const int wn   = (wid >> 2) * 64;    // warp N offset

    float acc[2][8][4];
    #pragma unroll
    for (int i = 0; i < 2; i++)
        #pragma unroll
        for (int j = 0; j < 8; j++)
            #pragma unroll
            for (int t = 0; t < 4; t++) acc[i][j][t] = 0.f;

    // global->smem fill indices: u = tid + 256*i ; row = u>>2 (0..127), seg = u&3
    const int r0 = tid >> 2;
    const int s0 = tid & 3;

    const __nv_bfloat16* Ab = A + (size_t)bm * KEFF;
    const __nv_bfloat16* Bb = B + (size_t)bn * KEFF;

    uint32_t a_s = smem_u32(&As[0][0]);
    uint32_t b_s = smem_u32(&Bs[0][0]);

    // ldmatrix lane addressing (element offsets)
    const int a_row  = wm + (lane & 15);
    const int a_koff = ((lane >> 4) & 1) * 8;
    const int b_row_base = wn + (lane & 7) + ((lane >> 4) & 1) * 8;
    const int b_koff = ((lane >> 3) & 1) * 8;

    // preload chunk 0
    {
        #pragma unroll
        for (int i = 0; i < 2; i++) {
            int row = r0 + 64 * i, seg = s0;
            uint4 va = *(const uint4*)(Ab + (size_t)row * KEFF + seg * 8);
            uint4 vb = *(const uint4*)(Bb + (size_t)row * KEFF + seg * 8);
            *(uint4*)((char*)&As[0][0] + row * 80 + seg * 16) = va;
            *(uint4*)((char*)&Bs[0][0] + row * 80 + seg * 16) = vb;
        }
    }
    __syncthreads();

    for (int c = 0; c < NCHUNK; c++) {
        const int buf = c & 1;
        uint4 pa[2], pb[2];
        if (c + 1 < NCHUNK) {
            const int kpos = (c + 1) * KC;
            #pragma unroll
            for (int i = 0; i < 2; i++) {
                int row = r0 + 64 * i, seg = s0;
                pa[i] = *(const uint4*)(Ab + (size_t)row * KEFF + kpos + seg * 8);
                pb[i] = *(const uint4*)(Bb + (size_t)row * KEFF + kpos + seg * 8);
            }
        }

        // compute chunk c
        uint32_t abase = a_s + buf * (BM * RSTRIDE * 2);
        uint32_t bbase = b_s + buf * (BN * RSTRIDE * 2);
        #pragma unroll
        for (int ks = 0; ks < 2; ks++) {
            const int kp = ks * 16;
            uint32_t af[2][4];
            #pragma unroll
            for (int mt = 0; mt < 2; mt++) {
                uint32_t addr = abase + (a_row + mt * 16) * 80 + (kp + a_koff) * 2;
                ldsm4(af[mt][0], af[mt][1], af[mt][2], af[mt][3], addr);
            }
            uint32_t bf[8][2];
            #pragma unroll
            for (int bt = 0; bt < 4; bt++) {
                uint32_t addr = bbase + (b_row_base + bt * 16) * 80 + (kp + b_koff) * 2;
                ldsm4(bf[2*bt][0], bf[2*bt][1], bf[2*bt+1][0], bf[2*bt+1][1], addr);
            }
            #pragma unroll
            for (int mt = 0; mt < 2; mt++)
                #pragma unroll
                for (int nt = 0; nt < 8; nt++)
                    mma16816(acc[mt][nt], af[mt], bf[nt]);
        }

        if (c + 1 < NCHUNK) {
            const int nbuf = buf ^ 1;
            #pragma unroll
            for (int i = 0; i < 2; i++) {
                int row = r0 + 64 * i, seg = s0;
                *(uint4*)((char*)&As[nbuf][0] + row * 80 + seg * 16) = pa[i];
                *(uint4*)((char*)&Bs[nbuf][0] + row * 80 + seg * 16) = pb[i];
            }
            __syncthreads();
        }
    }

    // epilogue: direct fp32 global stores
    const int cr = lane >> 2;        // 0..7
    const int cc = (lane & 3) * 2;   // 0,2,4,6
    #pragma unroll
    for (int mt = 0; mt < 2; mt++) {
        #pragma unroll
        for (int nt = 0; nt < 8; nt++) {
            float* p0 = C + (size_t)(bm + wm + mt * 16 + cr) * N + bn + wn + nt * 8 + cc;
            float* p1 = p0 + 8 * (size_t)N;
            p0[0] = acc[mt][nt][0]; p0[1] = acc[mt][nt][1];
            p1[0] = acc[mt][nt][2]; p1[1] = acc[mt][nt][3];
        }
    }
}

// ---------------- RoPE --------------------------------------------------------
__global__ void rope_table()
{
    int i = blockIdx.x * blockDim.x + threadIdx.x;
    if (i >= S_LEN * 32) return;
    int s = i >> 5, j = i & 31;
    float inv = (float)exp(-(double)j * (log(10000.0) / 32.0));
    float ang = (float)s * inv;
    float c, sn;
    sincosf(ang, &sn, &c);
    g_cos[i] = c;
    g_sin[i] = sn;
}

__global__ void rope_apply(float* __restrict__ buf, int heads, int total_pairs)
{
    int idx = blockIdx.x * blockDim.x + threadIdx.x;
    if (idx >= total_pairs) return;
    int j   = idx & 31;
    int t   = idx >> 5;
    int h   = t % heads;
    int row = t / heads;
    int s   = row & (S_LEN - 1);
    float c  = g_cos[(s << 5) + j];
    float sn = g_sin[(s << 5) + j];
    float* p = buf + (size_t)row * heads * HDIM + h * HDIM + j;
    float x1 = p[0], x2 = p[32];
    p[0]  = x1 * c - x2 * sn;
    p[32] = x2 * c + x1 * sn;
}

// ---------------- causal GQA flash attention (fp32) ---------------------------
__global__ __launch_bounds__(128)
void attn_kernel(const float* __restrict__ q, const float* __restrict__ k,
                 const float* __restrict__ v, float* __restrict__ ctx)
{
    __shared__ float k_s[32][64];
    __shared__ float v_s[32][64];

    const int qb  = blockIdx.x;
    const int h   = blockIdx.y;
    const int b   = blockIdx.z;
    const int kvh = h / GSIZE;
    const int tid = threadIdx.x;
    const int qg  = qb * 128 + tid;

    const float* qrow = q + ((size_t)b * S_LEN + qg) * D_MODEL + h * HDIM;
    float qreg[64];
    #pragma unroll
    for (int d = 0; d < 64; d += 4) {
        float4 t = *(const float4*)(qrow + d);
        qreg[d+0]=t.x; qreg[d+1]=t.y; qreg[d+2]=t.z; qreg[d+3]=t.w;
    }

    float m = -1e30f, l = 0.f;
    float acc[64];
    #pragma unroll
    for (int d = 0; d < 64; d++) acc[d] = 0.f;

    const float scale = 0.125f;
    const int nkb = 4 * qb + 4;
    const float* kbase = k + (size_t)b * S_LEN * KVD + kvh * HDIM;
    const float* vbase = v + (size_t)b * S_LEN * KVD + kvh * HDIM;

    for (int kb = 0; kb < nkb; kb++) {
        __syncthreads();
        #pragma unroll
        for (int r = 0; r < 4; r++) {
            int idx = tid + 128 * r;
            int row = idx >> 4;
            int c4  = (idx & 15) * 4;
            size_t goff = (size_t)(kb * 32 + row) * KVD + c4;
            *(float4*)(&k_s[row][c4]) = *(const float4*)(kbase + goff);
            *(float4*)(&v_s[row][c4]) = *(const float4*)(vbase + goff);
        }
        __syncthreads();

        float pbuf[32];
        float mb = -1e30f;
        #pragma unroll 4
        for (int ki = 0; ki < 32; ki++) {
            float s0 = 0.f, s1 = 0.f, s2 = 0.f, s3 = 0.f;
            #pragma unroll
            for (int d4 = 0; d4 < 16; d4++) {
                float4 kv = *(const float4*)(&k_s[ki][d4 * 4]);
                s0 += qreg[d4*4+0] * kv.x;
                s1 += qreg[d4*4+1] * kv.y;
                s2 += qreg[d4*4+2] * kv.z;
                s3 += qreg[d4*4+3] * kv.w;
            }
            float sum = (s0 + s1) + (s2 + s3);
            int kg = kb * 32 + ki;
            float sv = (kg <= qg) ? sum * scale : -1e30f;
            pbuf[ki] = sv;
            mb = fmaxf(mb, sv);
        }

        float mnew = fmaxf(m, mb);
        float corr = __expf(m - mnew);
        l *= corr;
        #pragma unroll
        for (int d = 0; d < 64; d++) acc[d] *= corr;

        #pragma unroll 4
        for (int ki = 0; ki < 32; ki++) {
            float p = __expf(pbuf[ki] - mnew);
            l += p;
            #pragma unroll
            for (int d4 = 0; d4 < 16; d4++) {
                float4 vv = *(const float4*)(&v_s[ki][d4 * 4]);
                acc[d4*4+0] += p * vv.x;
                acc[d4*4+1] += p * vv.y;
                acc[d4*4+2] += p * vv.z;
                acc[d4*4+3] += p * vv.w;
            }
        }
        m = mnew;
    }

    float invl = 1.f / l;
    float* out = ctx + ((size_t)b * S_LEN + qg) * D_MODEL + h * HDIM;
    #pragma unroll
    for (int d = 0; d < 64; d += 4) {
        float4 t;
        t.x = acc[d+0]*invl; t.y = acc[d+1]*invl;
        t.z = acc[d+2]*invl; t.w = acc[d+3]*invl;
        *(float4*)(out + d) = t;
    }
}

// ---------------- host launch -------------------------------------------------
extern "C" void kernel_launch(void* const* d_in, const int* in_sizes, int n_in,
                              void* d_out, int out_size)
{
    const float* x  = (const float*)d_in[0];
    const float* Wq = (const float*)d_in[1];
    const float* Wk = (const float*)d_in[2];
    const float* Wv = (const float*)d_in[3];
    const float* Wo = (const float*)d_in[4];
    float* out = (float*)d_out;

    float *q, *k, *v, *ctx;
    __nv_bfloat16 *ahat, *wq, *wk, *wv, *wo;
    cudaGetSymbolAddress((void**)&q,    g_q);
    cudaGetSymbolAddress((void**)&k,    g_k);
    cudaGetSymbolAddress((void**)&v,    g_v);
    cudaGetSymbolAddress((void**)&ctx,  g_ctx);
    cudaGetSymbolAddress((void**)&ahat, g_ahat);
    cudaGetSymbolAddress((void**)&wq,   g_wq);
    cudaGetSymbolAddress((void**)&wk,   g_wk);
    cudaGetSymbolAddress((void**)&wv,   g_wv);
    cudaGetSymbolAddress((void**)&wo,   g_wo);

    // conversions
    {
        int total = MROWS * KDIM;
        conv_split<<<(total + 255) / 256, 256>>>(x, ahat, total);
        dim3 blk(32, 32);
        conv_wt<<<dim3(D_MODEL / 32, KDIM / 32), blk>>>(Wq, wq, D_MODEL);
        conv_wt<<<dim3(KVD / 32,     KDIM / 32), blk>>>(Wk, wk, KVD);
        conv_wt<<<dim3(KVD / 32,     KDIM / 32), blk>>>(Wv, wv, KVD);
        conv_wt<<<dim3(D_MODEL / 32, KDIM / 32), blk>>>(Wo, wo, D_MODEL);
        rope_table<<<(S_LEN * 32 + 255) / 256, 256>>>();
    }

    // QKV projections (HMMA)
    gemm_hmma<<<dim3(D_MODEL / BN, MROWS / BM), 256>>>(ahat, wq, q, D_MODEL);
    gemm_hmma<<<dim3(KVD / BN,     MROWS / BM), 256>>>(ahat, wk, k, KVD);
    gemm_hmma<<<dim3(KVD / BN,     MROWS / BM), 256>>>(ahat, wv, v, KVD);

    // RoPE
    {
        int pairs_q = MROWS * NHEADS * 32;
        int pairs_k = MROWS * NKVH  * 32;
        rope_apply<<<(pairs_q + 255) / 256, 256>>>(q, NHEADS, pairs_q);
        rope_apply<<<(pairs_k + 255) / 256, 256>>>(k, NKVH,  pairs_k);
    }

    // attention
    attn_kernel<<<dim3(S_LEN / 128, NHEADS, BATCH), 128>>>(q, k, v, ctx);

    // output projection
    {
        int total = MROWS * KDIM;
        conv_split<<<(total + 255) / 256, 256>>>(ctx, ahat, total);
        gemm_hmma<<<dim3(D_MODEL / BN, MROWS / BM), 256>>>(ahat, wo, out, D_MODEL);
    }
}

// round 4
// speedup vs baseline: 3.1105x; 1.7359x over previous
#include <cuda_runtime.h>
#include <cuda_bf16.h>
#include <math.h>
#include <cstdint>

#define BATCH   2
#define S_LEN   2048
#define D_MODEL 2048
#define NHEADS  32
#define NKVH    8
#define HDIM    64
#define GSIZE   (NHEADS / NKVH)
#define KVD     (NKVH * HDIM)        // 512
#define MROWS   (BATCH * S_LEN)      // 4096
#define KDIM    2048
#define KEFF    (3 * KDIM)           // 6144 stacked K

// ---------------- scratch (device globals) ----------------------------------
__device__ float g_q  [MROWS * D_MODEL];
__device__ float g_k  [MROWS * KVD];
__device__ float g_v  [MROWS * KVD];
__device__ float g_ctx[MROWS * D_MODEL];
__device__ __nv_bfloat16 g_ahat[(size_t)MROWS  * KEFF];
__device__ __nv_bfloat16 g_wq [(size_t)D_MODEL * KEFF];
__device__ __nv_bfloat16 g_wk [(size_t)KVD     * KEFF];
__device__ __nv_bfloat16 g_wv [(size_t)KVD     * KEFF];
__device__ __nv_bfloat16 g_wo [(size_t)D_MODEL * KEFF];
__device__ float g_cos[S_LEN * 32];
__device__ float g_sin[S_LEN * 32];
// split-bf16 attention operands
__device__ __nv_bfloat16 g_qhi[MROWS * D_MODEL];
__device__ __nv_bfloat16 g_qlo[MROWS * D_MODEL];
__device__ __nv_bfloat16 g_khi[MROWS * KVD];
__device__ __nv_bfloat16 g_klo[MROWS * KVD];
__device__ __nv_bfloat16 g_vhi[MROWS * KVD];
__device__ __nv_bfloat16 g_vlo[MROWS * KVD];

// ---------------- helpers ------------------------------------------------
__device__ __forceinline__ uint32_t smem_u32(const void* p) {
    uint32_t a;
    asm("{ .reg .u64 t; cvta.to.shared.u64 t, %1; cvt.u32.u64 %0, t; }"
        : "=r"(a) : "l"(p));
    return a;
}

__device__ __forceinline__ void ldsm4(uint32_t& r0, uint32_t& r1, uint32_t& r2,
                                      uint32_t& r3, uint32_t addr) {
    asm volatile("ldmatrix.sync.aligned.m8n8.x4.shared.b16 {%0,%1,%2,%3}, [%4];"
                 : "=r"(r0), "=r"(r1), "=r"(r2), "=r"(r3) : "r"(addr));
}
__device__ __forceinline__ void ldsm4t(uint32_t& r0, uint32_t& r1, uint32_t& r2,
                                       uint32_t& r3, uint32_t addr) {
    asm volatile("ldmatrix.sync.aligned.m8n8.x4.trans.shared.b16 {%0,%1,%2,%3}, [%4];"
                 : "=r"(r0), "=r"(r1), "=r"(r2), "=r"(r3) : "r"(addr));
}

__device__ __forceinline__ void mma16816(float* d, const uint32_t* a, const uint32_t* b) {
    asm volatile(
        "mma.sync.aligned.m16n8k16.row.col.f32.bf16.bf16.f32 "
        "{%0,%1,%2,%3}, {%4,%5,%6,%7}, {%8,%9}, {%0,%1,%2,%3};"
        : "+f"(d[0]), "+f"(d[1]), "+f"(d[2]), "+f"(d[3])
        : "r"(a[0]), "r"(a[1]), "r"(a[2]), "r"(a[3]), "r"(b[0]), "r"(b[1]));
}

// pack two floats to bf16x2 (lo element in low half)
__device__ __forceinline__ uint32_t packbf(float lo_e, float hi_e) {
    uint32_t r;
    asm("cvt.rn.bf16x2.f32 %0, %1, %2;" : "=r"(r) : "f"(hi_e), "f"(lo_e));
    return r;
}

// ---------------- conversion kernels -----------------------------------------
__global__ void conv_split(const float* __restrict__ in, __nv_bfloat16* __restrict__ out,
                           int total)
{
    int i = blockIdx.x * blockDim.x + threadIdx.x;
    if (i >= total) return;
    int row = i / KDIM, col = i - row * KDIM;
    float v = in[i];
    __nv_bfloat16 hi = __float2bfloat16(v);
    __nv_bfloat16 lo = __float2bfloat16(v - __bfloat162float(hi));
    size_t base = (size_t)row * KEFF + col;
    out[base]            = hi;
    out[base + KDIM]     = lo;
    out[base + 2 * KDIM] = hi;
}

__global__ void conv_wt(const float* __restrict__ W, __nv_bfloat16* __restrict__ out, int N)
{
    __shared__ float tile[32][33];
    int k0 = blockIdx.y * 32, n0 = blockIdx.x * 32;
    int tx = threadIdx.x, ty = threadIdx.y;
    tile[ty][tx] = W[(size_t)(k0 + ty) * N + n0 + tx];
    __syncthreads();
    float v = tile[tx][ty];
    __nv_bfloat16 hi = __float2bfloat16(v);
    __nv_bfloat16 lo = __float2bfloat16(v - __bfloat162float(hi));
    size_t base = (size_t)(n0 + ty) * KEFF + k0 + tx;
    out[base]            = hi;
    out[base + KDIM]     = hi;
    out[base + 2 * KDIM] = lo;
}

// ---------------- HMMA bf16 GEMM (unchanged from R3) ------------------------
#define BM 128
#define BN 128
#define KC 32
#define NCHUNK (KEFF / KC)
#define RSTRIDE 40

__global__ __launch_bounds__(256)
void gemm_hmma(const __nv_bfloat16* __restrict__ A, const __nv_bfloat16* __restrict__ B,
               float* __restrict__ C, int N)
{
    __shared__ __nv_bfloat16 As[2][BM * RSTRIDE];
    __shared__ __nv_bfloat16 Bs[2][BN * RSTRIDE];

    const int tid  = threadIdx.x;
    const int wid  = tid >> 5;
    const int lane = tid & 31;
    const int bm   = blockIdx.y * BM;
    const int bn   = blockIdx.x * BN;
    const int wm   = (wid & 3) * 32;
    const int wn   = (wid >> 2) * 64;

    float acc[2][8][4];
    #pragma unroll
    for (int i = 0; i < 2; i++)
        #pragma unroll
        for (int j = 0; j < 8; j++)
            #pragma unroll
            for (int t = 0; t < 4; t++) acc[i][j][t] = 0.f;

    const int r0 = tid >> 2;
    const int s0 = tid & 3;

    const __nv_bfloat16* Ab = A + (size_t)bm * KEFF;
    const __nv_bfloat16* Bb = B + (size_t)bn * KEFF;

    uint32_t a_s = smem_u32(&As[0][0]);
    uint32_t b_s = smem_u32(&Bs[0][0]);

    const int a_row  = wm + (lane & 15);
    const int a_koff = ((lane >> 4) & 1) * 8;
    const int b_row_base = wn + (lane & 7) + ((lane >> 4) & 1) * 8;
    const int b_koff = ((lane >> 3) & 1) * 8;

    {
        #pragma unroll
        for (int i = 0; i < 2; i++) {
            int row = r0 + 64 * i, seg = s0;
            uint4 va = *(const uint4*)(Ab + (size_t)row * KEFF + seg * 8);
            uint4 vb = *(const uint4*)(Bb + (size_t)row * KEFF + seg * 8);
            *(uint4*)((char*)&As[0][0] + row * 80 + seg * 16) = va;
            *(uint4*)((char*)&Bs[0][0] + row * 80 + seg * 16) = vb;
        }
    }
    __syncthreads();

    for (int c = 0; c < NCHUNK; c++) {
        const int buf = c & 1;
        uint4 pa[2], pb[2];
        if (c + 1 < NCHUNK) {
            const int kpos = (c + 1) * KC;
            #pragma unroll
            for (int i = 0; i < 2; i++) {
                int row = r0 + 64 * i, seg = s0;
                pa[i] = *(const uint4*)(Ab + (size_t)row * KEFF + kpos + seg * 8);
                pb[i] = *(const uint4*)(Bb + (size_t)row * KEFF + kpos + seg * 8);
            }
        }

        uint32_t abase = a_s + buf * (BM * RSTRIDE * 2);
        uint32_t bbase = b_s + buf * (BN * RSTRIDE * 2);
        #pragma unroll
        for (int ks = 0; ks < 2; ks++) {
            const int kp = ks * 16;
            uint32_t af[2][4];
            #pragma unroll
            for (int mt = 0; mt < 2; mt++) {
                uint32_t addr = abase + (a_row + mt * 16) * 80 + (kp + a_koff) * 2;
                ldsm4(af[mt][0], af[mt][1], af[mt][2], af[mt][3], addr);
            }
            uint32_t bf[8][2];
            #pragma unroll
            for (int bt = 0; bt < 4; bt++) {
                uint32_t addr = bbase + (b_row_base + bt * 16) * 80 + (kp + b_koff) * 2;
                ldsm4(bf[2*bt][0], bf[2*bt][1], bf[2*bt+1][0], bf[2*bt+1][1], addr);
            }
            #pragma unroll
            for (int mt = 0; mt < 2; mt++)
                #pragma unroll
                for (int nt = 0; nt < 8; nt++)
                    mma16816(acc[mt][nt], af[mt], bf[nt]);
        }

        if (c + 1 < NCHUNK) {
            const int nbuf = buf ^ 1;
            #pragma unroll
            for (int i = 0; i < 2; i++) {
                int row = r0 + 64 * i, seg = s0;
                *(uint4*)((char*)&As[nbuf][0] + row * 80 + seg * 16) = pa[i];
                *(uint4*)((char*)&Bs[nbuf][0] + row * 80 + seg * 16) = pb[i];
            }
            __syncthreads();
        }
    }

    const int cr = lane >> 2;
    const int cc = (lane & 3) * 2;
    #pragma unroll
    for (int mt = 0; mt < 2; mt++) {
        #pragma unroll
        for (int nt = 0; nt < 8; nt++) {
            float* p0 = C + (size_t)(bm + wm + mt * 16 + cr) * N + bn + wn + nt * 8 + cc;
            float* p1 = p0 + 8 * (size_t)N;
            p0[0] = acc[mt][nt][0]; p0[1] = acc[mt][nt][1];
            p1[0] = acc[mt][nt][2]; p1[1] = acc[mt][nt][3];
        }
    }
}

// ---------------- RoPE --------------------------------------------------------
__global__ void rope_table()
{
    int i = blockIdx.x * blockDim.x + threadIdx.x;
    if (i >= S_LEN * 32) return;
    int s = i >> 5, j = i & 31;
    float inv = (float)exp(-(double)j * (log(10000.0) / 32.0));
    float ang = (float)s * inv;
    float c, sn;
    sincosf(ang, &sn, &c);
    g_cos[i] = c;
    g_sin[i] = sn;
}

// RoPE + split to bf16 hi/lo (with optional prescale folded in)
__global__ void rope_split(const float* __restrict__ src,
                           __nv_bfloat16* __restrict__ hi, __nv_bfloat16* __restrict__ lo,
                           int heads, float prescale, int total_pairs)
{
    int idx = blockIdx.x * blockDim.x + threadIdx.x;
    if (idx >= total_pairs) return;
    int j   = idx & 31;
    int t   = idx >> 5;
    int h   = t % heads;
    int row = t / heads;
    int s   = row & (S_LEN - 1);
    float c  = g_cos[(s << 5) + j];
    float sn = g_sin[(s << 5) + j];
    size_t off = (size_t)row * heads * HDIM + h * HDIM + j;
    float x1 = src[off], x2 = src[off + 32];
    float y1 = (x1 * c - x2 * sn) * prescale;
    float y2 = (x2 * c + x1 * sn) * prescale;
    __nv_bfloat16 h1 = __float2bfloat16(y1);
    __nv_bfloat16 h2 = __float2bfloat16(y2);
    hi[off]      = h1;
    hi[off + 32] = h2;
    lo[off]      = __float2bfloat16(y1 - __bfloat162float(h1));
    lo[off + 32] = __float2bfloat16(y2 - __bfloat162float(h2));
}

__global__ void v_split(const float* __restrict__ src,
                        __nv_bfloat16* __restrict__ hi, __nv_bfloat16* __restrict__ lo,
                        int total)
{
    int i = blockIdx.x * blockDim.x + threadIdx.x;
    if (i >= total) return;
    float v = src[i];
    __nv_bfloat16 h = __float2bfloat16(v);
    hi[i] = h;
    lo[i] = __float2bfloat16(v - __bfloat162float(h));
}

// ---------------- HMMA causal GQA flash attention -----------------------------
// CTA: 128 q rows, 8 warps (m16 each), 64-key tiles.
// smem (union): Q phase: qhi[128][72], qlo[128][72]; KV phase: khi/klo/vhi/vlo [64][72].
#define AT_STRB 144   // bytes per smem row (72 bf16)

__global__ __launch_bounds__(256, 1)
void attn_hmma(const __nv_bfloat16* __restrict__ qhi, const __nv_bfloat16* __restrict__ qlo,
               const __nv_bfloat16* __restrict__ khi, const __nv_bfloat16* __restrict__ klo,
               const __nv_bfloat16* __restrict__ vhi, const __nv_bfloat16* __restrict__ vlo,
               float* __restrict__ ctx)
{
    __shared__ __align__(16) char sm[4 * 64 * AT_STRB];   // 36864 B

    const int qb  = gridDim.x - 1 - blockIdx.x;   // heavy blocks first
    const int h   = blockIdx.y;
    const int b   = blockIdx.z;
    const int kvh = h / GSIZE;
    const int tid = threadIdx.x;
    const int wid = tid >> 5;
    const int lane = tid & 31;
    const int qrow0 = qb * 128;
    const int wm = wid * 16;

    const uint32_t sbase = smem_u32(sm);

    // ---- Q phase: load 128x64 hi+lo into smem
    {
        const __nv_bfloat16* srcs[2] = {qhi, qlo};
        #pragma unroll
        for (int arr = 0; arr < 2; arr++) {
            const __nv_bfloat16* s = srcs[arr];
            #pragma unroll
            for (int i = 0; i < 4; i++) {
                int u = tid + 256 * i;       // 0..1023
                int row = u >> 3, seg = u & 7;
                uint4 v = *(const uint4*)(s + ((size_t)(b * S_LEN + qrow0 + row)) * D_MODEL
                                            + h * HDIM + seg * 8);
                *(uint4*)(sm + arr * (128 * AT_STRB) + row * AT_STRB + seg * 16) = v;
            }
        }
    }
    __syncthreads();

    // extract persistent Q fragments
    uint32_t qh[4][4], ql[4][4];
    {
        uint32_t arow = (uint32_t)(wm + (lane & 15));
        uint32_t koff = ((lane >> 4) & 1) * 8;
        #pragma unroll
        for (int kc = 0; kc < 4; kc++) {
            uint32_t a0 = sbase + arow * AT_STRB + (kc * 16 + koff) * 2;
            ldsm4(qh[kc][0], qh[kc][1], qh[kc][2], qh[kc][3], a0);
            ldsm4(ql[kc][0], ql[kc][1], ql[kc][2], ql[kc][3], a0 + 128 * AT_STRB);
        }
    }

    float m0 = -1e30f, m1 = -1e30f, l0 = 0.f, l1 = 0.f;
    float ctxa[8][4];
    #pragma unroll
    for (int t = 0; t < 8; t++)
        #pragma unroll
        for (int j = 0; j < 4; j++) ctxa[t][j] = 0.f;

    const int nkt = 2 * qb + 2;
    const int KOFF = 0, KLOFF = 64 * AT_STRB, VOFF = 2 * 64 * AT_STRB, VLOFF = 3 * 64 * AT_STRB;

    for (int kt = 0; kt < nkt; kt++) {
        const int k0 = kt * 64;
        __syncthreads();   // previous tile fully consumed (also guards Q smem on kt=0)
        {
            const __nv_bfloat16* srcs[4] = {khi, klo, vhi, vlo};
            #pragma unroll
            for (int arr = 0; arr < 4; arr++) {
                const __nv_bfloat16* s = srcs[arr];
                #pragma unroll
                for (int i = 0; i < 2; i++) {
                    int u = tid + 256 * i;   // 0..511
                    int row = u >> 3, seg = u & 7;
                    uint4 v = *(const uint4*)(s + ((size_t)(b * S_LEN + k0 + row)) * KVD
                                                + kvh * HDIM + seg * 8);
                    *(uint4*)(sm + arr * (64 * AT_STRB) + row * AT_STRB + seg * 16) = v;
                }
            }
        }
        __syncthreads();

        if (k0 <= qrow0 + wm + 15) {
            // ---------- QK: S = Qhi*Khi + Qlo*Khi + Qhi*Klo
            float sc[8][4];
            #pragma unroll
            for (int t = 0; t < 8; t++)
                #pragma unroll
                for (int j = 0; j < 4; j++) sc[t][j] = 0.f;

            #pragma unroll
            for (int g = 0; g < 4; g++) {
                uint32_t kh[4][4], kl_[4][4];
                #pragma unroll
                for (int kc = 0; kc < 4; kc++) {
                    uint32_t addr = sbase + KOFF
                        + (g * 16 + (lane & 7) + ((lane >> 4) & 1) * 8) * AT_STRB
                        + (kc * 16 + ((lane >> 3) & 1) * 8) * 2;
                    ldsm4(kh[kc][0], kh[kc][1], kh[kc][2], kh[kc][3], addr);
                    ldsm4(kl_[kc][0], kl_[kc][1], kl_[kc][2], kl_[kc][3], addr + KLOFF);
                }
                #pragma unroll
                for (int kc = 0; kc < 4; kc++) {
                    uint32_t bh0[2] = {kh[kc][0], kh[kc][1]};
                    uint32_t bh1[2] = {kh[kc][2], kh[kc][3]};
                    uint32_t bl0[2] = {kl_[kc][0], kl_[kc][1]};
                    uint32_t bl1[2] = {kl_[kc][2], kl_[kc][3]};
                    mma16816(sc[2*g],   qh[kc], bh0);
                    mma16816(sc[2*g],   ql[kc], bh0);
                    mma16816(sc[2*g],   qh[kc], bl0);
                    mma16816(sc[2*g+1], qh[kc], bh1);
                    mma16816(sc[2*g+1], ql[kc], bh1);
                    mma16816(sc[2*g+1], qh[kc], bl1);
                }
            }

            // ---------- mask (diagonal tiles only)
            const int rtop = qrow0 + wm + (lane >> 2);
            const int rbot = rtop + 8;
            if (kt >= nkt - 2) {
                #pragma unroll
                for (int t = 0; t < 8; t++) {
                    int kg = k0 + t * 8 + (lane & 3) * 2;
                    if (kg     > rtop) sc[t][0] = -1e30f;
                    if (kg + 1 > rtop) sc[t][1] = -1e30f;
                    if (kg     > rbot) sc[t][2] = -1e30f;
                    if (kg + 1 > rbot) sc[t][3] = -1e30f;
                }
            }

            // ---------- online softmax
            float tm0 = -1e30f, tm1 = -1e30f;
            #pragma unroll
            for (int t = 0; t < 8; t++) {
                tm0 = fmaxf(tm0, fmaxf(sc[t][0], sc[t][1]));
                tm1 = fmaxf(tm1, fmaxf(sc[t][2], sc[t][3]));
            }
            tm0 = fmaxf(tm0, __shfl_xor_sync(0xFFFFFFFFu, tm0, 1));
            tm0 = fmaxf(tm0, __shfl_xor_sync(0xFFFFFFFFu, tm0, 2));
            tm1 = fmaxf(tm1, __shfl_xor_sync(0xFFFFFFFFu, tm1, 1));
            tm1 = fmaxf(tm1, __shfl_xor_sync(0xFFFFFFFFu, tm1, 2));
            float mn0 = fmaxf(m0, tm0), mn1 = fmaxf(m1, tm1);
            float c0 = __expf(m0 - mn0), c1 = __expf(m1 - mn1);
            m0 = mn0; m1 = mn1;
            l0 *= c0;  l1 *= c1;
            #pragma unroll
            for (int t = 0; t < 8; t++) {
                ctxa[t][0] *= c0; ctxa[t][1] *= c0;
                ctxa[t][2] *= c1; ctxa[t][3] *= c1;
            }

            float ps0 = 0.f, ps1 = 0.f;
            uint32_t ph[4][4], pl[4][4];
            #pragma unroll
            for (int t = 0; t < 8; t++) {
                float p0 = __expf(sc[t][0] - mn0);
                float p1 = __expf(sc[t][1] - mn0);
                float p2 = __expf(sc[t][2] - mn1);
                float p3 = __expf(sc[t][3] - mn1);
                ps0 += p0 + p1; ps1 += p2 + p3;
                uint32_t hp01 = packbf(p0, p1);
                uint32_t hp23 = packbf(p2, p3);
                float f0 = __uint_as_float(hp01 << 16);
                float f1 = __uint_as_float(hp01 & 0xFFFF0000u);
                float f2 = __uint_as_float(hp23 << 16);
                float f3 = __uint_as_float(hp23 & 0xFFFF0000u);
                uint32_t lp01 = packbf(p0 - f0, p1 - f1);
                uint32_t lp23 = packbf(p2 - f2, p3 - f3);
                int kc = t >> 1, hf = (t & 1) * 2;
                ph[kc][hf]     = hp01;  ph[kc][hf + 1] = hp23;
                pl[kc][hf]     = lp01;  pl[kc][hf + 1] = lp23;
            }
            ps0 += __shfl_xor_sync(0xFFFFFFFFu, ps0, 1);
            ps0 += __shfl_xor_sync(0xFFFFFFFFu, ps0, 2);
            ps1 += __shfl_xor_sync(0xFFFFFFFFu, ps1, 1);
            ps1 += __shfl_xor_sync(0xFFFFFFFFu, ps1, 2);
            l0 += ps0; l1 += ps1;

            // ---------- PV: O += Phi*Vhi + Plo*Vhi + Phi*Vlo
            #pragma unroll
            for (int kc = 0; kc < 4; kc++) {
                #pragma unroll
                for (int g = 0; g < 4; g++) {
                    uint32_t vh[4], vl[4];
                    uint32_t addr = sbase + VOFF
                        + (kc * 16 + (lane & 7) + ((lane >> 3) & 1) * 8) * AT_STRB
                        + (g * 16 + ((lane >> 4) & 1) * 8) * 2;
                    ldsm4t(vh[0], vh[1], vh[2], vh[3], addr);
                    ldsm4t(vl[0], vl[1], vl[2], vl[3], addr + (VLOFF - VOFF));
                    uint32_t bh0[2] = {vh[0], vh[1]};
                    uint32_t bh1[2] = {vh[2], vh[3]};
                    uint32_t bl0[2] = {vl[0], vl[1]};
                    uint32_t bl1[2] = {vl[2], vl[3]};
                    mma16816(ctxa[2*g],   ph[kc], bh0);
                    mma16816(ctxa[2*g],   pl[kc], bh0);
                    mma16816(ctxa[2*g],   ph[kc], bl0);
                    mma16816(ctxa[2*g+1], ph[kc], bh1);
                    mma16816(ctxa[2*g+1], pl[kc], bh1);
                    mma16816(ctxa[2*g+1], ph[kc], bl1);
                }
            }
        }
    }

    // ---------- epilogue
    float il0 = 1.f / l0, il1 = 1.f / l1;
    const int rtop = qrow0 + wm + (lane >> 2);
    float* c0p = ctx + ((size_t)(b * S_LEN) + rtop) * D_MODEL + h * HDIM;
    float* c1p = c0p + 8 * (size_t)D_MODEL;
    #pragma unroll
    for (int t = 0; t < 8; t++) {
        int col = t * 8 + (lane & 3) * 2;
        c0p[col]     = ctxa[t][0] * il0;
        c0p[col + 1] = ctxa[t][1] * il0;
        c1p[col]     = ctxa[t][2] * il1;
        c1p[col + 1] = ctxa[t][3] * il1;
    }
}

// ---------------- host launch -------------------------------------------------
extern "C" void kernel_launch(void* const* d_in, const int* in_sizes, int n_in,
                              void* d_out, int out_size)
{
    const float* x  = (const float*)d_in[0];
    const float* Wq = (const float*)d_in[1];
    const float* Wk = (const float*)d_in[2];
    const float* Wv = (const float*)d_in[3];
    const float* Wo = (const float*)d_in[4];
    float* out = (float*)d_out;

    float *q, *k, *v, *ctx;
    __nv_bfloat16 *ahat, *wq, *wk, *wv, *wo;
    __nv_bfloat16 *qhi, *qlo, *khi, *klo, *vhi, *vlo;
    cudaGetSymbolAddress((void**)&q,    g_q);
    cudaGetSymbolAddress((void**)&k,    g_k);
    cudaGetSymbolAddress((void**)&v,    g_v);
    cudaGetSymbolAddress((void**)&ctx,  g_ctx);
    cudaGetSymbolAddress((void**)&ahat, g_ahat);
    cudaGetSymbolAddress((void**)&wq,   g_wq);
    cudaGetSymbolAddress((void**)&wk,   g_wk);
    cudaGetSymbolAddress((void**)&wv,   g_wv);
    cudaGetSymbolAddress((void**)&wo,   g_wo);
    cudaGetSymbolAddress((void**)&qhi,  g_qhi);
    cudaGetSymbolAddress((void**)&qlo,  g_qlo);
    cudaGetSymbolAddress((void**)&khi,  g_khi);
    cudaGetSymbolAddress((void**)&klo,  g_klo);
    cudaGetSymbolAddress((void**)&vhi,  g_vhi);
    cudaGetSymbolAddress((void**)&vlo,  g_vlo);

    // conversions
    {
        int total = MROWS * KDIM;
        conv_split<<<(total + 255) / 256, 256>>>(x, ahat, total);
        dim3 blk(32, 32);
        conv_wt<<<dim3(D_MODEL / 32, KDIM / 32), blk>>>(Wq, wq, D_MODEL);
        conv_wt<<<dim3(KVD / 32,     KDIM / 32), blk>>>(Wk, wk, KVD);
        conv_wt<<<dim3(KVD / 32,     KDIM / 32), blk>>>(Wv, wv, KVD);
        conv_wt<<<dim3(D_MODEL / 32, KDIM / 32), blk>>>(Wo, wo, D_MODEL);
        rope_table<<<(S_LEN * 32 + 255) / 256, 256>>>();
    }

    // QKV projections (HMMA)
    gemm_hmma<<<dim3(D_MODEL / BN, MROWS / BM), 256>>>(ahat, wq, q, D_MODEL);
    gemm_hmma<<<dim3(KVD / BN,     MROWS / BM), 256>>>(ahat, wk, k, KVD);
    gemm_hmma<<<dim3(KVD / BN,     MROWS / BM), 256>>>(ahat, wv, v, KVD);

    // RoPE + split to bf16 (q prescaled by 1/sqrt(HD) = 0.125)
    {
        int pairs_q = MROWS * NHEADS * 32;
        int pairs_k = MROWS * NKVH  * 32;
        rope_split<<<(pairs_q + 255) / 256, 256>>>(q, qhi, qlo, NHEADS, 0.125f, pairs_q);
        rope_split<<<(pairs_k + 255) / 256, 256>>>(k, khi, klo, NKVH, 1.0f,  pairs_k);
        int tv = MROWS * KVD;
        v_split<<<(tv + 255) / 256, 256>>>(v, vhi, vlo, tv);
    }

    // HMMA attention
    attn_hmma<<<dim3(S_LEN / 128, NHEADS, BATCH), 256>>>(qhi, qlo, khi, klo, vhi, vlo, ctx);

    // output projection
    {
        int total = MROWS * KDIM;
        conv_split<<<(total + 255) / 256, 256>>>(ctx, ahat, total);
        gemm_hmma<<<dim3(D_MODEL / BN, MROWS / BM), 256>>>(ahat, wo, out, D_MODEL);
    }
}

// round 5
// speedup vs baseline: 3.1609x; 1.0162x over previous
#include <cuda_runtime.h>
#include <cuda_bf16.h>
#include <math.h>
#include <cstdint>

#define BATCH   2
#define S_LEN   2048
#define D_MODEL 2048
#define NHEADS  32
#define NKVH    8
#define HDIM    64
#define GSIZE   (NHEADS / NKVH)
#define KVD     (NKVH * HDIM)        // 512
#define MROWS   (BATCH * S_LEN)      // 4096
#define KDIM    2048
#define KEFF    (3 * KDIM)           // 6144 stacked K

// ---------------- scratch (device globals) ----------------------------------
__device__ float g_q  [MROWS * D_MODEL];
__device__ float g_k  [MROWS * KVD];
__device__ float g_v  [MROWS * KVD];
__device__ float g_ctx[MROWS * D_MODEL];
__device__ __nv_bfloat16 g_ahat[(size_t)MROWS  * KEFF];
__device__ __nv_bfloat16 g_wq [(size_t)D_MODEL * KEFF];
__device__ __nv_bfloat16 g_wk [(size_t)KVD     * KEFF];
__device__ __nv_bfloat16 g_wv [(size_t)KVD     * KEFF];
__device__ __nv_bfloat16 g_wo [(size_t)D_MODEL * KEFF];
__device__ float g_cos[S_LEN * 32];
__device__ float g_sin[S_LEN * 32];
__device__ __nv_bfloat16 g_qhi[MROWS * D_MODEL];
__device__ __nv_bfloat16 g_qlo[MROWS * D_MODEL];
__device__ __nv_bfloat16 g_khi[MROWS * KVD];
__device__ __nv_bfloat16 g_klo[MROWS * KVD];
__device__ __nv_bfloat16 g_vhi[MROWS * KVD];
__device__ __nv_bfloat16 g_vlo[MROWS * KVD];

// ---------------- helpers ------------------------------------------------
__device__ __forceinline__ uint32_t smem_u32(const void* p) {
    uint32_t a;
    asm("{ .reg .u64 t; cvta.to.shared.u64 t, %1; cvt.u32.u64 %0, t; }"
        : "=r"(a) : "l"(p));
    return a;
}

__device__ __forceinline__ void cp16(uint32_t saddr, const void* gaddr) {
    asm volatile("cp.async.cg.shared.global [%0], [%1], 16;"
                 :: "r"(saddr), "l"(gaddr) : "memory");
}
#define CP_COMMIT() asm volatile("cp.async.commit_group;" ::: "memory")
#define CP_WAIT(n)  asm volatile("cp.async.wait_group %0;" :: "n"(n) : "memory")

__device__ __forceinline__ void ldsm4(uint32_t& r0, uint32_t& r1, uint32_t& r2,
                                      uint32_t& r3, uint32_t addr) {
    asm volatile("ldmatrix.sync.aligned.m8n8.x4.shared.b16 {%0,%1,%2,%3}, [%4];"
                 : "=r"(r0), "=r"(r1), "=r"(r2), "=r"(r3) : "r"(addr));
}
__device__ __forceinline__ void ldsm4t(uint32_t& r0, uint32_t& r1, uint32_t& r2,
                                       uint32_t& r3, uint32_t addr) {
    asm volatile("ldmatrix.sync.aligned.m8n8.x4.trans.shared.b16 {%0,%1,%2,%3}, [%4];"
                 : "=r"(r0), "=r"(r1), "=r"(r2), "=r"(r3) : "r"(addr));
}

__device__ __forceinline__ void mma16816(float* d, const uint32_t* a, const uint32_t* b) {
    asm volatile(
        "mma.sync.aligned.m16n8k16.row.col.f32.bf16.bf16.f32 "
        "{%0,%1,%2,%3}, {%4,%5,%6,%7}, {%8,%9}, {%0,%1,%2,%3};"
        : "+f"(d[0]), "+f"(d[1]), "+f"(d[2]), "+f"(d[3])
        : "r"(a[0]), "r"(a[1]), "r"(a[2]), "r"(a[3]), "r"(b[0]), "r"(b[1]));
}

__device__ __forceinline__ uint32_t packbf(float lo_e, float hi_e) {
    uint32_t r;
    asm("cvt.rn.bf16x2.f32 %0, %1, %2;" : "=r"(r) : "f"(hi_e), "f"(lo_e));
    return r;
}

// ---------------- conversion kernels -----------------------------------------
__global__ void conv_split(const float* __restrict__ in, __nv_bfloat16* __restrict__ out,
                           int total)
{
    int i = blockIdx.x * blockDim.x + threadIdx.x;
    if (i >= total) return;
    int row = i / KDIM, col = i - row * KDIM;
    float v = in[i];
    __nv_bfloat16 hi = __float2bfloat16(v);
    __nv_bfloat16 lo = __float2bfloat16(v - __bfloat162float(hi));
    size_t base = (size_t)row * KEFF + col;
    out[base]            = hi;
    out[base + KDIM]     = lo;
    out[base + 2 * KDIM] = hi;
}

__global__ void conv_wt(const float* __restrict__ W, __nv_bfloat16* __restrict__ out, int N)
{
    __shared__ float tile[32][33];
    int k0 = blockIdx.y * 32, n0 = blockIdx.x * 32;
    int tx = threadIdx.x, ty = threadIdx.y;
    tile[ty][tx] = W[(size_t)(k0 + ty) * N + n0 + tx];
    __syncthreads();
    float v = tile[tx][ty];
    __nv_bfloat16 hi = __float2bfloat16(v);
    __nv_bfloat16 lo = __float2bfloat16(v - __bfloat162float(hi));
    size_t base = (size_t)(n0 + ty) * KEFF + k0 + tx;
    out[base]            = hi;
    out[base + KDIM]     = hi;
    out[base + 2 * KDIM] = lo;
}

// ---------------- multistage cp.async HMMA GEMM ------------------------------
// C[M,N] = Ahat[M,6144] @ Bhat[N,6144]^T ; block 128x128, 8 warps, KC=32, 4 stages
#define BM 128
#define BN 128
#define KC 32
#define NCHUNK (KEFF / KC)     // 192
#define STAGES 4
#define STG_A  10240           // 128 rows * 80 B
#define STG_SZ 20480           // A + B per stage
#define GSMEM  (STAGES * STG_SZ)   // 81920

__global__ __launch_bounds__(256)
void gemm_hmma(const __nv_bfloat16* __restrict__ A, const __nv_bfloat16* __restrict__ B,
               float* __restrict__ C, int N)
{
    extern __shared__ char gsm[];
    const uint32_t sbase = smem_u32(gsm);

    const int tid  = threadIdx.x;
    const int wid  = tid >> 5;
    const int lane = tid & 31;
    const int bm   = blockIdx.y * BM;
    const int bn   = blockIdx.x * BN;
    const int wm   = (wid & 3) * 32;
    const int wn   = (wid >> 2) * 64;

    float acc[2][8][4];
    #pragma unroll
    for (int i = 0; i < 2; i++)
        #pragma unroll
        for (int j = 0; j < 8; j++)
            #pragma unroll
            for (int t = 0; t < 4; t++) acc[i][j][t] = 0.f;

    const int r0 = tid >> 2;       // 0..63
    const int s0 = tid & 3;        // 0..3

    const __nv_bfloat16* Ab = A + (size_t)bm * KEFF;
    const __nv_bfloat16* Bb = B + (size_t)bn * KEFF;

    const int a_row  = wm + (lane & 15);
    const int a_koff = ((lane >> 4) & 1) * 8;
    const int b_row_base = wn + (lane & 7) + ((lane >> 4) & 1) * 8;
    const int b_koff = ((lane >> 3) & 1) * 8;

    // fill chunk c into slot
    auto fill = [&](int c, int slot) {
        const int kpos = c * KC;
        const uint32_t abase = sbase + slot * STG_SZ;
        const uint32_t bbase = abase + STG_A;
        #pragma unroll
        for (int i = 0; i < 2; i++) {
            int row = r0 + 64 * i, seg = s0;
            cp16(abase + row * 80 + seg * 16, Ab + (size_t)row * KEFF + kpos + seg * 8);
            cp16(bbase + row * 80 + seg * 16, Bb + (size_t)row * KEFF + kpos + seg * 8);
        }
    };

    #pragma unroll
    for (int s = 0; s < STAGES - 1; s++) {
        fill(s, s);
        CP_COMMIT();
    }

    for (int c = 0; c < NCHUNK; c++) {
        CP_WAIT(STAGES - 2);
        __syncthreads();

        // issue next fill (slot freed at iteration c-1)
        if (c + STAGES - 1 < NCHUNK)
            fill(c + STAGES - 1, (c + STAGES - 1) % STAGES);
        CP_COMMIT();

        // compute chunk c
        const int slot = c % STAGES;
        const uint32_t abase = sbase + slot * STG_SZ;
        const uint32_t bbase = abase + STG_A;
        #pragma unroll
        for (int ks = 0; ks < 2; ks++) {
            const int kp = ks * 16;
            uint32_t af[2][4];
            #pragma unroll
            for (int mt = 0; mt < 2; mt++) {
                uint32_t addr = abase + (a_row + mt * 16) * 80 + (kp + a_koff) * 2;
                ldsm4(af[mt][0], af[mt][1], af[mt][2], af[mt][3], addr);
            }
            uint32_t bf[8][2];
            #pragma unroll
            for (int bt = 0; bt < 4; bt++) {
                uint32_t addr = bbase + (b_row_base + bt * 16) * 80 + (kp + b_koff) * 2;
                ldsm4(bf[2*bt][0], bf[2*bt][1], bf[2*bt+1][0], bf[2*bt+1][1], addr);
            }
            #pragma unroll
            for (int mt = 0; mt < 2; mt++)
                #pragma unroll
                for (int nt = 0; nt < 8; nt++)
                    mma16816(acc[mt][nt], af[mt], bf[nt]);
        }
    }

    const int cr = lane >> 2;
    const int cc = (lane & 3) * 2;
    #pragma unroll
    for (int mt = 0; mt < 2; mt++) {
        #pragma unroll
        for (int nt = 0; nt < 8; nt++) {
            float* p0 = C + (size_t)(bm + wm + mt * 16 + cr) * N + bn + wn + nt * 8 + cc;
            float* p1 = p0 + 8 * (size_t)N;
            p0[0] = acc[mt][nt][0]; p0[1] = acc[mt][nt][1];
            p1[0] = acc[mt][nt][2]; p1[1] = acc[mt][nt][3];
        }
    }
}

// ---------------- RoPE --------------------------------------------------------
__global__ void rope_table()
{
    int i = blockIdx.x * blockDim.x + threadIdx.x;
    if (i >= S_LEN * 32) return;
    int s = i >> 5, j = i & 31;
    float inv = (float)exp(-(double)j * (log(10000.0) / 32.0));
    float ang = (float)s * inv;
    float c, sn;
    sincosf(ang, &sn, &c);
    g_cos[i] = c;
    g_sin[i] = sn;
}

__global__ void rope_split(const float* __restrict__ src,
                           __nv_bfloat16* __restrict__ hi, __nv_bfloat16* __restrict__ lo,
                           int heads, float prescale, int total_pairs)
{
    int idx = blockIdx.x * blockDim.x + threadIdx.x;
    if (idx >= total_pairs) return;
    int j   = idx & 31;
    int t   = idx >> 5;
    int h   = t % heads;
    int row = t / heads;
    int s   = row & (S_LEN - 1);
    float c  = g_cos[(s << 5) + j];
    float sn = g_sin[(s << 5) + j];
    size_t off = (size_t)row * heads * HDIM + h * HDIM + j;
    float x1 = src[off], x2 = src[off + 32];
    float y1 = (x1 * c - x2 * sn) * prescale;
    float y2 = (x2 * c + x1 * sn) * prescale;
    __nv_bfloat16 h1 = __float2bfloat16(y1);
    __nv_bfloat16 h2 = __float2bfloat16(y2);
    hi[off]      = h1;
    hi[off + 32] = h2;
    lo[off]      = __float2bfloat16(y1 - __bfloat162float(h1));
    lo[off + 32] = __float2bfloat16(y2 - __bfloat162float(h2));
}

__global__ void v_split(const float* __restrict__ src,
                        __nv_bfloat16* __restrict__ hi, __nv_bfloat16* __restrict__ lo,
                        int total)
{
    int i = blockIdx.x * blockDim.x + threadIdx.x;
    if (i >= total) return;
    float v = src[i];
    __nv_bfloat16 h = __float2bfloat16(v);
    hi[i] = h;
    lo[i] = __float2bfloat16(v - __bfloat162float(h));
}

// ---------------- HMMA causal GQA flash attention (unchanged from R4) --------
#define AT_STRB 144

__global__ __launch_bounds__(256, 1)
void attn_hmma(const __nv_bfloat16* __restrict__ qhi, const __nv_bfloat16* __restrict__ qlo,
               const __nv_bfloat16* __restrict__ khi, const __nv_bfloat16* __restrict__ klo,
               const __nv_bfloat16* __restrict__ vhi, const __nv_bfloat16* __restrict__ vlo,
               float* __restrict__ ctx)
{
    __shared__ __align__(16) char sm[4 * 64 * AT_STRB];

    const int qb  = gridDim.x - 1 - blockIdx.x;
    const int h   = blockIdx.y;
    const int b   = blockIdx.z;
    const int kvh = h / GSIZE;
    const int tid = threadIdx.x;
    const int wid = tid >> 5;
    const int lane = tid & 31;
    const int qrow0 = qb * 128;
    const int wm = wid * 16;

    const uint32_t sbase = smem_u32(sm);

    {
        const __nv_bfloat16* srcs[2] = {qhi, qlo};
        #pragma unroll
        for (int arr = 0; arr < 2; arr++) {
            const __nv_bfloat16* s = srcs[arr];
            #pragma unroll
            for (int i = 0; i < 4; i++) {
                int u = tid + 256 * i;
                int row = u >> 3, seg = u & 7;
                uint4 v = *(const uint4*)(s + ((size_t)(b * S_LEN + qrow0 + row)) * D_MODEL
                                            + h * HDIM + seg * 8);
                *(uint4*)(sm + arr * (128 * AT_STRB) + row * AT_STRB + seg * 16) = v;
            }
        }
    }
    __syncthreads();

    uint32_t qh[4][4], ql[4][4];
    {
        uint32_t arow = (uint32_t)(wm + (lane & 15));
        uint32_t koff = ((lane >> 4) & 1) * 8;
        #pragma unroll
        for (int kc = 0; kc < 4; kc++) {
            uint32_t a0 = sbase + arow * AT_STRB + (kc * 16 + koff) * 2;
            ldsm4(qh[kc][0], qh[kc][1], qh[kc][2], qh[kc][3], a0);
            ldsm4(ql[kc][0], ql[kc][1], ql[kc][2], ql[kc][3], a0 + 128 * AT_STRB);
        }
    }

    float m0 = -1e30f, m1 = -1e30f, l0 = 0.f, l1 = 0.f;
    float ctxa[8][4];
    #pragma unroll
    for (int t = 0; t < 8; t++)
        #pragma unroll
        for (int j = 0; j < 4; j++) ctxa[t][j] = 0.f;

    const int nkt = 2 * qb + 2;
    const int KOFF = 0, KLOFF = 64 * AT_STRB, VOFF = 2 * 64 * AT_STRB, VLOFF = 3 * 64 * AT_STRB;

    for (int kt = 0; kt < nkt; kt++) {
        const int k0 = kt * 64;
        __syncthreads();
        {
            const __nv_bfloat16* srcs[4] = {khi, klo, vhi, vlo};
            #pragma unroll
            for (int arr = 0; arr < 4; arr++) {
                const __nv_bfloat16* s = srcs[arr];
                #pragma unroll
                for (int i = 0; i < 2; i++) {
                    int u = tid + 256 * i;
                    int row = u >> 3, seg = u & 7;
                    uint4 v = *(const uint4*)(s + ((size_t)(b * S_LEN + k0 + row)) * KVD
                                                + kvh * HDIM + seg * 8);
                    *(uint4*)(sm + arr * (64 * AT_STRB) + row * AT_STRB + seg * 16) = v;
                }
            }
        }
        __syncthreads();

        if (k0 <= qrow0 + wm + 15) {
            float sc[8][4];
            #pragma unroll
            for (int t = 0; t < 8; t++)
                #pragma unroll
                for (int j = 0; j < 4; j++) sc[t][j] = 0.f;

            #pragma unroll
            for (int g = 0; g < 4; g++) {
                uint32_t kh[4][4], kl_[4][4];
                #pragma unroll
                for (int kc = 0; kc < 4; kc++) {
                    uint32_t addr = sbase + KOFF
                        + (g * 16 + (lane & 7) + ((lane >> 4) & 1) * 8) * AT_STRB
                        + (kc * 16 + ((lane >> 3) & 1) * 8) * 2;
                    ldsm4(kh[kc][0], kh[kc][1], kh[kc][2], kh[kc][3], addr);
                    ldsm4(kl_[kc][0], kl_[kc][1], kl_[kc][2], kl_[kc][3], addr + KLOFF);
                }
                #pragma unroll
                for (int kc = 0; kc < 4; kc++) {
                    uint32_t bh0[2] = {kh[kc][0], kh[kc][1]};
                    uint32_t bh1[2] = {kh[kc][2], kh[kc][3]};
                    uint32_t bl0[2] = {kl_[kc][0], kl_[kc][1]};
                    uint32_t bl1[2] = {kl_[kc][2], kl_[kc][3]};
                    mma16816(sc[2*g],   qh[kc], bh0);
                    mma16816(sc[2*g],   ql[kc], bh0);
                    mma16816(sc[2*g],   qh[kc], bl0);
                    mma16816(sc[2*g+1], qh[kc], bh1);
                    mma16816(sc[2*g+1], ql[kc], bh1);
                    mma16816(sc[2*g+1], qh[kc], bl1);
                }
            }

            const int rtop = qrow0 + wm + (lane >> 2);
            const int rbot = rtop + 8;
            if (kt >= nkt - 2) {
                #pragma unroll
                for (int t = 0; t < 8; t++) {
                    int kg = k0 + t * 8 + (lane & 3) * 2;
                    if (kg     > rtop) sc[t][0] = -1e30f;
                    if (kg + 1 > rtop) sc[t][1] = -1e30f;
                    if (kg     > rbot) sc[t][2] = -1e30f;
                    if (kg + 1 > rbot) sc[t][3] = -1e30f;
                }
            }

            float tm0 = -1e30f, tm1 = -1e30f;
            #pragma unroll
            for (int t = 0; t < 8; t++) {
                tm0 = fmaxf(tm0, fmaxf(sc[t][0], sc[t][1]));
                tm1 = fmaxf(tm1, fmaxf(sc[t][2], sc[t][3]));
            }
            tm0 = fmaxf(tm0, __shfl_xor_sync(0xFFFFFFFFu, tm0, 1));
            tm0 = fmaxf(tm0, __shfl_xor_sync(0xFFFFFFFFu, tm0, 2));
            tm1 = fmaxf(tm1, __shfl_xor_sync(0xFFFFFFFFu, tm1, 1));
            tm1 = fmaxf(tm1, __shfl_xor_sync(0xFFFFFFFFu, tm1, 2));
            float mn0 = fmaxf(m0, tm0), mn1 = fmaxf(m1, tm1);
            float c0 = __expf(m0 - mn0), c1 = __expf(m1 - mn1);
            m0 = mn0; m1 = mn1;
            l0 *= c0;  l1 *= c1;
            #pragma unroll
            for (int t = 0; t < 8; t++) {
                ctxa[t][0] *= c0; ctxa[t][1] *= c0;
                ctxa[t][2] *= c1; ctxa[t][3] *= c1;
            }

            float ps0 = 0.f, ps1 = 0.f;
            uint32_t ph[4][4], pl[4][4];
            #pragma unroll
            for (int t = 0; t < 8; t++) {
                float p0 = __expf(sc[t][0] - mn0);
                float p1 = __expf(sc[t][1] - mn0);
                float p2 = __expf(sc[t][2] - mn1);
                float p3 = __expf(sc[t][3] - mn1);
                ps0 += p0 + p1; ps1 += p2 + p3;
                uint32_t hp01 = packbf(p0, p1);
                uint32_t hp23 = packbf(p2, p3);
                float f0 = __uint_as_float(hp01 << 16);
                float f1 = __uint_as_float(hp01 & 0xFFFF0000u);
                float f2 = __uint_as_float(hp23 << 16);
                float f3 = __uint_as_float(hp23 & 0xFFFF0000u);
                uint32_t lp01 = packbf(p0 - f0, p1 - f1);
                uint32_t lp23 = packbf(p2 - f2, p3 - f3);
                int kc = t >> 1, hf = (t & 1) * 2;
                ph[kc][hf]     = hp01;  ph[kc][hf + 1] = hp23;
                pl[kc][hf]     = lp01;  pl[kc][hf + 1] = lp23;
            }
            ps0 += __shfl_xor_sync(0xFFFFFFFFu, ps0, 1);
            ps0 += __shfl_xor_sync(0xFFFFFFFFu, ps0, 2);
            ps1 += __shfl_xor_sync(0xFFFFFFFFu, ps1, 1);
            ps1 += __shfl_xor_sync(0xFFFFFFFFu, ps1, 2);
            l0 += ps0; l1 += ps1;

            #pragma unroll
            for (int kc = 0; kc < 4; kc++) {
                #pragma unroll
                for (int g = 0; g < 4; g++) {
                    uint32_t vh[4], vl[4];
                    uint32_t addr = sbase + VOFF
                        + (kc * 16 + (lane & 7) + ((lane >> 3) & 1) * 8) * AT_STRB
                        + (g * 16 + ((lane >> 4) & 1) * 8) * 2;
                    ldsm4t(vh[0], vh[1], vh[2], vh[3], addr);
                    ldsm4t(vl[0], vl[1], vl[2], vl[3], addr + (VLOFF - VOFF));
                    uint32_t bh0[2] = {vh[0], vh[1]};
                    uint32_t bh1[2] = {vh[2], vh[3]};
                    uint32_t bl0[2] = {vl[0], vl[1]};
                    uint32_t bl1[2] = {vl[2], vl[3]};
                    mma16816(ctxa[2*g],   ph[kc], bh0);
                    mma16816(ctxa[2*g],   pl[kc], bh0);
                    mma16816(ctxa[2*g],   ph[kc], bl0);
                    mma16816(ctxa[2*g+1], ph[kc], bh1);
                    mma16816(ctxa[2*g+1], pl[kc], bh1);
                    mma16816(ctxa[2*g+1], ph[kc], bl1);
                }
            }
        }
    }

    float il0 = 1.f / l0, il1 = 1.f / l1;
    const int rtop = qrow0 + wm + (lane >> 2);
    float* c0p = ctx + ((size_t)(b * S_LEN) + rtop) * D_MODEL + h * HDIM;
    float* c1p = c0p + 8 * (size_t)D_MODEL;
    #pragma unroll
    for (int t = 0; t < 8; t++) {
        int col = t * 8 + (lane & 3) * 2;
        c0p[col]     = ctxa[t][0] * il0;
        c0p[col + 1] = ctxa[t][1] * il0;
        c1p[col]     = ctxa[t][2] * il1;
        c1p[col + 1] = ctxa[t][3] * il1;
    }
}

// ---------------- host launch -------------------------------------------------
extern "C" void kernel_launch(void* const* d_in, const int* in_sizes, int n_in,
                              void* d_out, int out_size)
{
    const float* x  = (const float*)d_in[0];
    const float* Wq = (const float*)d_in[1];
    const float* Wk = (const float*)d_in[2];
    const float* Wv = (const float*)d_in[3];
    const float* Wo = (const float*)d_in[4];
    float* out = (float*)d_out;

    float *q, *k, *v, *ctx;
    __nv_bfloat16 *ahat, *wq, *wk, *wv, *wo;
    __nv_bfloat16 *qhi, *qlo, *khi, *klo, *vhi, *vlo;
    cudaGetSymbolAddress((void**)&q,    g_q);
    cudaGetSymbolAddress((void**)&k,    g_k);
    cudaGetSymbolAddress((void**)&v,    g_v);
    cudaGetSymbolAddress((void**)&ctx,  g_ctx);
    cudaGetSymbolAddress((void**)&ahat, g_ahat);
    cudaGetSymbolAddress((void**)&wq,   g_wq);
    cudaGetSymbolAddress((void**)&wk,   g_wk);
    cudaGetSymbolAddress((void**)&wv,   g_wv);
    cudaGetSymbolAddress((void**)&wo,   g_wo);
    cudaGetSymbolAddress((void**)&qhi,  g_qhi);
    cudaGetSymbolAddress((void**)&qlo,  g_qlo);
    cudaGetSymbolAddress((void**)&khi,  g_khi);
    cudaGetSymbolAddress((void**)&klo,  g_klo);
    cudaGetSymbolAddress((void**)&vhi,  g_vhi);
    cudaGetSymbolAddress((void**)&vlo,  g_vlo);

    static int smem_set = 0;
    if (!smem_set) {
        cudaFuncSetAttribute(gemm_hmma, cudaFuncAttributeMaxDynamicSharedMemorySize, GSMEM);
        smem_set = 1;
    }

    // conversions
    {
        int total = MROWS * KDIM;
        conv_split<<<(total + 255) / 256, 256>>>(x, ahat, total);
        dim3 blk(32, 32);
        conv_wt<<<dim3(D_MODEL / 32, KDIM / 32), blk>>>(Wq, wq, D_MODEL);
        conv_wt<<<dim3(KVD / 32,     KDIM / 32), blk>>>(Wk, wk, KVD);
        conv_wt<<<dim3(KVD / 32,     KDIM / 32), blk>>>(Wv, wv, KVD);
        conv_wt<<<dim3(D_MODEL / 32, KDIM / 32), blk>>>(Wo, wo, D_MODEL);
        rope_table<<<(S_LEN * 32 + 255) / 256, 256>>>();
    }

    // QKV projections (HMMA, multistage)
    gemm_hmma<<<dim3(D_MODEL / BN, MROWS / BM), 256, GSMEM>>>(ahat, wq, q, D_MODEL);
    gemm_hmma<<<dim3(KVD / BN,     MROWS / BM), 256, GSMEM>>>(ahat, wk, k, KVD);
    gemm_hmma<<<dim3(KVD / BN,     MROWS / BM), 256, GSMEM>>>(ahat, wv, v, KVD);

    // RoPE + split to bf16
    {
        int pairs_q = MROWS * NHEADS * 32;
        int pairs_k = MROWS * NKVH  * 32;
        rope_split<<<(pairs_q + 255) / 256, 256>>>(q, qhi, qlo, NHEADS, 0.125f, pairs_q);
        rope_split<<<(pairs_k + 255) / 256, 256>>>(k, khi, klo, NKVH, 1.0f,  pairs_k);
        int tv = MROWS * KVD;
        v_split<<<(tv + 255) / 256, 256>>>(v, vhi, vlo, tv);
    }

    // HMMA attention
    attn_hmma<<<dim3(S_LEN / 128, NHEADS, BATCH), 256>>>(qhi, qlo, khi, klo, vhi, vlo, ctx);

    // output projection
    {
        int total = MROWS * KDIM;
        conv_split<<<(total + 255) / 256, 256>>>(ctx, ahat, total);
        gemm_hmma<<<dim3(D_MODEL / BN, MROWS / BM), 256, GSMEM>>>(ahat, wo, out, D_MODEL);
    }
}

// round 6
// speedup vs baseline: 4.3979x; 1.3913x over previous
#include <cuda_runtime.h>
#include <cuda_fp16.h>
#include <math.h>
#include <cstdint>

#define BATCH   2
#define S_LEN   2048
#define D_MODEL 2048
#define NHEADS  32
#define NKVH    8
#define HDIM    64
#define GSIZE   (NHEADS / NKVH)
#define KVD     (NKVH * HDIM)        // 512
#define MROWS   (BATCH * S_LEN)      // 4096
#define KDIM    2048
#define KEFF2   (2 * KDIM)           // 4096 stacked K (hi|lo)

// ---------------- scratch (device globals) ----------------------------------
__device__ float g_q  [MROWS * D_MODEL];
__device__ float g_k  [MROWS * KVD];
__device__ float g_v  [MROWS * KVD];
__device__ float g_ctx[MROWS * D_MODEL];
__device__ __half g_ahat[(size_t)MROWS  * KEFF2];   // activations: hi|lo
__device__ __half g_wq [(size_t)D_MODEL * KDIM];    // weights: hi only (transposed)
__device__ __half g_wk [(size_t)KVD     * KDIM];
__device__ __half g_wv [(size_t)KVD     * KDIM];
__device__ __half g_wo [(size_t)D_MODEL * KDIM];
__device__ float g_cos[S_LEN * 32];
__device__ float g_sin[S_LEN * 32];
__device__ __half g_qhi[MROWS * D_MODEL];
__device__ __half g_qlo[MROWS * D_MODEL];
__device__ __half g_khi[MROWS * KVD];
__device__ __half g_vhi[MROWS * KVD];

// ---------------- helpers ------------------------------------------------
__device__ __forceinline__ uint32_t smem_u32(const void* p) {
    uint32_t a;
    asm("{ .reg .u64 t; cvta.to.shared.u64 t, %1; cvt.u32.u64 %0, t; }"
        : "=r"(a) : "l"(p));
    return a;
}

__device__ __forceinline__ void cp16(uint32_t saddr, const void* gaddr) {
    asm volatile("cp.async.cg.shared.global [%0], [%1], 16;"
                 :: "r"(saddr), "l"(gaddr) : "memory");
}
#define CP_COMMIT() asm volatile("cp.async.commit_group;" ::: "memory")
#define CP_WAIT(n)  asm volatile("cp.async.wait_group %0;" :: "n"(n) : "memory")

__device__ __forceinline__ void ldsm4(uint32_t& r0, uint32_t& r1, uint32_t& r2,
                                      uint32_t& r3, uint32_t addr) {
    asm volatile("ldmatrix.sync.aligned.m8n8.x4.shared.b16 {%0,%1,%2,%3}, [%4];"
                 : "=r"(r0), "=r"(r1), "=r"(r2), "=r"(r3) : "r"(addr));
}
__device__ __forceinline__ void ldsm4t(uint32_t& r0, uint32_t& r1, uint32_t& r2,
                                       uint32_t& r3, uint32_t addr) {
    asm volatile("ldmatrix.sync.aligned.m8n8.x4.trans.shared.b16 {%0,%1,%2,%3}, [%4];"
                 : "=r"(r0), "=r"(r1), "=r"(r2), "=r"(r3) : "r"(addr));
}

__device__ __forceinline__ void mma16816(float* d, const uint32_t* a, const uint32_t* b) {
    asm volatile(
        "mma.sync.aligned.m16n8k16.row.col.f32.f16.f16.f32 "
        "{%0,%1,%2,%3}, {%4,%5,%6,%7}, {%8,%9}, {%0,%1,%2,%3};"
        : "+f"(d[0]), "+f"(d[1]), "+f"(d[2]), "+f"(d[3])
        : "r"(a[0]), "r"(a[1]), "r"(a[2]), "r"(a[3]), "r"(b[0]), "r"(b[1]));
}

// pack two floats to fp16x2 (first arg -> low half)
__device__ __forceinline__ uint32_t pack2h(float lo_e, float hi_e) {
    __half2 h = __floats2half2_rn(lo_e, hi_e);
    return *reinterpret_cast<uint32_t*>(&h);
}

// ---------------- conversion kernels -----------------------------------------
// fp32 [rows][2048] -> fp16 [rows][4096] stacked (hi | lo)
__global__ void conv_split(const float* __restrict__ in, __half* __restrict__ out,
                           int total)
{
    int i = blockIdx.x * blockDim.x + threadIdx.x;
    if (i >= total) return;
    int row = i / KDIM, col = i - row * KDIM;
    float v = in[i];
    __half hi = __float2half_rn(v);
    __half lo = __float2half_rn(v - __half2float(hi));
    size_t base = (size_t)row * KEFF2 + col;
    out[base]        = hi;
    out[base + KDIM] = lo;
}

// W fp32 [2048][N] -> fp16 [N][2048] transposed (hi only)
__global__ void conv_wt(const float* __restrict__ W, __half* __restrict__ out, int N)
{
    __shared__ float tile[32][33];
    int k0 = blockIdx.y * 32, n0 = blockIdx.x * 32;
    int tx = threadIdx.x, ty = threadIdx.y;
    tile[ty][tx] = W[(size_t)(k0 + ty) * N + n0 + tx];
    __syncthreads();
    out[(size_t)(n0 + ty) * KDIM + k0 + tx] = __float2half_rn(tile[tx][ty]);
}

// ---------------- multistage cp.async HMMA GEMM ------------------------------
// C[M,N] = Ahat[M,4096] @ Bhi[N,2048]^T-wrapped ; 128x128 CTA, 8 warps, KC=32, 4 stages
#define BM 128
#define BN 128
#define KC 32
#define NCHUNK (KEFF2 / KC)    // 128
#define STAGES 4
#define STG_A  10240           // 128 rows * 80 B
#define STG_SZ 20480
#define GSMEM  (STAGES * STG_SZ)

__global__ __launch_bounds__(256)
void gemm_hmma(const __half* __restrict__ A, const __half* __restrict__ B,
               float* __restrict__ C, int N)
{
    extern __shared__ char gsm[];
    const uint32_t sbase = smem_u32(gsm);

    const int tid  = threadIdx.x;
    const int wid  = tid >> 5;
    const int lane = tid & 31;
    const int bm   = blockIdx.y * BM;
    const int bn   = blockIdx.x * BN;
    const int wm   = (wid & 3) * 32;
    const int wn   = (wid >> 2) * 64;

    float acc[2][8][4];
    #pragma unroll
    for (int i = 0; i < 2; i++)
        #pragma unroll
        for (int j = 0; j < 8; j++)
            #pragma unroll
            for (int t = 0; t < 4; t++) acc[i][j][t] = 0.f;

    const int r0 = tid >> 2;
    const int s0 = tid & 3;

    const __half* Ab = A + (size_t)bm * KEFF2;
    const __half* Bb = B + (size_t)bn * KDIM;

    const int a_row  = wm + (lane & 15);
    const int a_koff = ((lane >> 4) & 1) * 8;
    const int b_row_base = wn + (lane & 7) + ((lane >> 4) & 1) * 8;
    const int b_koff = ((lane >> 3) & 1) * 8;

    auto fill = [&](int c, int slot) {
        const int kposA = c * KC;
        const int kposB = kposA & (KDIM - 1);   // B wraps: hi reused for lo half
        const uint32_t abase = sbase + slot * STG_SZ;
        const uint32_t bbase = abase + STG_A;
        #pragma unroll
        for (int i = 0; i < 2; i++) {
            int row = r0 + 64 * i, seg = s0;
            cp16(abase + row * 80 + seg * 16, Ab + (size_t)row * KEFF2 + kposA + seg * 8);
            cp16(bbase + row * 80 + seg * 16, Bb + (size_t)row * KDIM  + kposB + seg * 8);
        }
    };

    #pragma unroll
    for (int s = 0; s < STAGES - 1; s++) {
        fill(s, s);
        CP_COMMIT();
    }

    for (int c = 0; c < NCHUNK; c++) {
        CP_WAIT(STAGES - 2);
        __syncthreads();

        if (c + STAGES - 1 < NCHUNK)
            fill(c + STAGES - 1, (c + STAGES - 1) % STAGES);
        CP_COMMIT();

        const int slot = c % STAGES;
        const uint32_t abase = sbase + slot * STG_SZ;
        const uint32_t bbase = abase + STG_A;
        #pragma unroll
        for (int ks = 0; ks < 2; ks++) {
            const int kp = ks * 16;
            uint32_t af[2][4];
            #pragma unroll
            for (int mt = 0; mt < 2; mt++) {
                uint32_t addr = abase + (a_row + mt * 16) * 80 + (kp + a_koff) * 2;
                ldsm4(af[mt][0], af[mt][1], af[mt][2], af[mt][3], addr);
            }
            uint32_t bf[8][2];
            #pragma unroll
            for (int bt = 0; bt < 4; bt++) {
                uint32_t addr = bbase + (b_row_base + bt * 16) * 80 + (kp + b_koff) * 2;
                ldsm4(bf[2*bt][0], bf[2*bt][1], bf[2*bt+1][0], bf[2*bt+1][1], addr);
            }
            #pragma unroll
            for (int mt = 0; mt < 2; mt++)
                #pragma unroll
                for (int nt = 0; nt < 8; nt++)
                    mma16816(acc[mt][nt], af[mt], bf[nt]);
        }
    }

    const int cr = lane >> 2;
    const int cc = (lane & 3) * 2;
    #pragma unroll
    for (int mt = 0; mt < 2; mt++) {
        #pragma unroll
        for (int nt = 0; nt < 8; nt++) {
            float* p0 = C + (size_t)(bm + wm + mt * 16 + cr) * N + bn + wn + nt * 8 + cc;
            float* p1 = p0 + 8 * (size_t)N;
            p0[0] = acc[mt][nt][0]; p0[1] = acc[mt][nt][1];
            p1[0] = acc[mt][nt][2]; p1[1] = acc[mt][nt][3];
        }
    }
}

// ---------------- RoPE --------------------------------------------------------
__global__ void rope_table()
{
    int i = blockIdx.x * blockDim.x + threadIdx.x;
    if (i >= S_LEN * 32) return;
    int s = i >> 5, j = i & 31;
    float inv = (float)exp(-(double)j * (log(10000.0) / 32.0));
    float ang = (float)s * inv;
    float c, sn;
    sincosf(ang, &sn, &c);
    g_cos[i] = c;
    g_sin[i] = sn;
}

// q: RoPE + prescale + fp16 hi/lo split
__global__ void rope_split_q(const float* __restrict__ src,
                             __half* __restrict__ hi, __half* __restrict__ lo,
                             int total_pairs)
{
    int idx = blockIdx.x * blockDim.x + threadIdx.x;
    if (idx >= total_pairs) return;
    int j   = idx & 31;
    int t   = idx >> 5;
    int h   = t % NHEADS;
    int row = t / NHEADS;
    int s   = row & (S_LEN - 1);
    float c  = g_cos[(s << 5) + j];
    float sn = g_sin[(s << 5) + j];
    size_t off = (size_t)row * D_MODEL + h * HDIM + j;
    float x1 = src[off], x2 = src[off + 32];
    float y1 = (x1 * c - x2 * sn) * 0.125f;
    float y2 = (x2 * c + x1 * sn) * 0.125f;
    __half h1 = __float2half_rn(y1);
    __half h2 = __float2half_rn(y2);
    hi[off]      = h1;
    hi[off + 32] = h2;
    lo[off]      = __float2half_rn(y1 - __half2float(h1));
    lo[off + 32] = __float2half_rn(y2 - __half2float(h2));
}

// k: RoPE + fp16 (hi only)
__global__ void rope_half_k(const float* __restrict__ src, __half* __restrict__ hi,
                            int total_pairs)
{
    int idx = blockIdx.x * blockDim.x + threadIdx.x;
    if (idx >= total_pairs) return;
    int j   = idx & 31;
    int t   = idx >> 5;
    int h   = t % NKVH;
    int row = t / NKVH;
    int s   = row & (S_LEN - 1);
    float c  = g_cos[(s << 5) + j];
    float sn = g_sin[(s << 5) + j];
    size_t off = (size_t)row * KVD + h * HDIM + j;
    float x1 = src[off], x2 = src[off + 32];
    hi[off]      = __float2half_rn(x1 * c - x2 * sn);
    hi[off + 32] = __float2half_rn(x2 * c + x1 * sn);
}

__global__ void v_half(const float* __restrict__ src, __half* __restrict__ hi, int total)
{
    int i = blockIdx.x * blockDim.x + threadIdx.x;
    if (i >= total) return;
    hi[i] = __float2half_rn(src[i]);
}

// ---------------- HMMA causal GQA flash attention -----------------------------
// CTA: 128 q rows, 8 warps (m16 each), 64-key tiles. Q hi+lo; K,V hi only.
#define AT_STRB 144

__global__ __launch_bounds__(256, 1)
void attn_hmma(const __half* __restrict__ qhi, const __half* __restrict__ qlo,
               const __half* __restrict__ khi, const __half* __restrict__ vhi,
               float* __restrict__ ctx)
{
    __shared__ __align__(16) char sm[2 * 128 * AT_STRB];   // Q phase 2x128 rows; KV phase 2x64 rows

    const int qb  = gridDim.x - 1 - blockIdx.x;
    const int h   = blockIdx.y;
    const int b   = blockIdx.z;
    const int kvh = h / GSIZE;
    const int tid = threadIdx.x;
    const int wid = tid >> 5;
    const int lane = tid & 31;
    const int qrow0 = qb * 128;
    const int wm = wid * 16;

    const uint32_t sbase = smem_u32(sm);

    // ---- Q phase
    {
        const __half* srcs[2] = {qhi, qlo};
        #pragma unroll
        for (int arr = 0; arr < 2; arr++) {
            const __half* s = srcs[arr];
            #pragma unroll
            for (int i = 0; i < 4; i++) {
                int u = tid + 256 * i;
                int row = u >> 3, seg = u & 7;
                uint4 v = *(const uint4*)(s + ((size_t)(b * S_LEN + qrow0 + row)) * D_MODEL
                                            + h * HDIM + seg * 8);
                *(uint4*)(sm + arr * (128 * AT_STRB) + row * AT_STRB + seg * 16) = v;
            }
        }
    }
    __syncthreads();

    uint32_t qh[4][4], ql[4][4];
    {
        uint32_t arow = (uint32_t)(wm + (lane & 15));
        uint32_t koff = ((lane >> 4) & 1) * 8;
        #pragma unroll
        for (int kc = 0; kc < 4; kc++) {
            uint32_t a0 = sbase + arow * AT_STRB + (kc * 16 + koff) * 2;
            ldsm4(qh[kc][0], qh[kc][1], qh[kc][2], qh[kc][3], a0);
            ldsm4(ql[kc][0], ql[kc][1], ql[kc][2], ql[kc][3], a0 + 128 * AT_STRB);
        }
    }

    float m0 = -1e30f, m1 = -1e30f, l0 = 0.f, l1 = 0.f;
    float ctxa[8][4];
    #pragma unroll
    for (int t = 0; t < 8; t++)
        #pragma unroll
        for (int j = 0; j < 4; j++) ctxa[t][j] = 0.f;

    const int nkt = 2 * qb + 2;
    const int VOFF = 64 * AT_STRB;   // khi at 0, vhi at VOFF

    for (int kt = 0; kt < nkt; kt++) {
        const int k0 = kt * 64;
        __syncthreads();
        {
            const __half* srcs[2] = {khi, vhi};
            #pragma unroll
            for (int arr = 0; arr < 2; arr++) {
                const __half* s = srcs[arr];
                #pragma unroll
                for (int i = 0; i < 2; i++) {
                    int u = tid + 256 * i;
                    int row = u >> 3, seg = u & 7;
                    uint4 v = *(const uint4*)(s + ((size_t)(b * S_LEN + k0 + row)) * KVD
                                                + kvh * HDIM + seg * 8);
                    *(uint4*)(sm + arr * VOFF + row * AT_STRB + seg * 16) = v;
                }
            }
        }
        __syncthreads();

        if (k0 <= qrow0 + wm + 15) {
            // ---------- QK: S = (Qhi + Qlo) * Khi
            float sc[8][4];
            #pragma unroll
            for (int t = 0; t < 8; t++)
                #pragma unroll
                for (int j = 0; j < 4; j++) sc[t][j] = 0.f;

            #pragma unroll
            for (int g = 0; g < 4; g++) {
                uint32_t kh[4][4];
                #pragma unroll
                for (int kc = 0; kc < 4; kc++) {
                    uint32_t addr = sbase
                        + (g * 16 + (lane & 7) + ((lane >> 4) & 1) * 8) * AT_STRB
                        + (kc * 16 + ((lane >> 3) & 1) * 8) * 2;
                    ldsm4(kh[kc][0], kh[kc][1], kh[kc][2], kh[kc][3], addr);
                }
                #pragma unroll
                for (int kc = 0; kc < 4; kc++) {
                    uint32_t bh0[2] = {kh[kc][0], kh[kc][1]};
                    uint32_t bh1[2] = {kh[kc][2], kh[kc][3]};
                    mma16816(sc[2*g],   qh[kc], bh0);
                    mma16816(sc[2*g],   ql[kc], bh0);
                    mma16816(sc[2*g+1], qh[kc], bh1);
                    mma16816(sc[2*g+1], ql[kc], bh1);
                }
            }

            const int rtop = qrow0 + wm + (lane >> 2);
            const int rbot = rtop + 8;
            if (kt >= nkt - 2) {
                #pragma unroll
                for (int t = 0; t < 8; t++) {
                    int kg = k0 + t * 8 + (lane & 3) * 2;
                    if (kg     > rtop) sc[t][0] = -1e30f;
                    if (kg + 1 > rtop) sc[t][1] = -1e30f;
                    if (kg     > rbot) sc[t][2] = -1e30f;
                    if (kg + 1 > rbot) sc[t][3] = -1e30f;
                }
            }

            float tm0 = -1e30f, tm1 = -1e30f;
            #pragma unroll
            for (int t = 0; t < 8; t++) {
                tm0 = fmaxf(tm0, fmaxf(sc[t][0], sc[t][1]));
                tm1 = fmaxf(tm1, fmaxf(sc[t][2], sc[t][3]));
            }
            tm0 = fmaxf(tm0, __shfl_xor_sync(0xFFFFFFFFu, tm0, 1));
            tm0 = fmaxf(tm0, __shfl_xor_sync(0xFFFFFFFFu, tm0, 2));
            tm1 = fmaxf(tm1, __shfl_xor_sync(0xFFFFFFFFu, tm1, 1));
            tm1 = fmaxf(tm1, __shfl_xor_sync(0xFFFFFFFFu, tm1, 2));
            float mn0 = fmaxf(m0, tm0), mn1 = fmaxf(m1, tm1);
            float c0 = __expf(m0 - mn0), c1 = __expf(m1 - mn1);
            m0 = mn0; m1 = mn1;
            l0 *= c0;  l1 *= c1;
            #pragma unroll
            for (int t = 0; t < 8; t++) {
                ctxa[t][0] *= c0; ctxa[t][1] *= c0;
                ctxa[t][2] *= c1; ctxa[t][3] *= c1;
            }

            float ps0 = 0.f, ps1 = 0.f;
            uint32_t ph[4][4], pl[4][4];
            #pragma unroll
            for (int t = 0; t < 8; t++) {
                float p0 = __expf(sc[t][0] - mn0);
                float p1 = __expf(sc[t][1] - mn0);
                float p2 = __expf(sc[t][2] - mn1);
                float p3 = __expf(sc[t][3] - mn1);
                ps0 += p0 + p1; ps1 += p2 + p3;
                uint32_t hp01 = pack2h(p0, p1);
                uint32_t hp23 = pack2h(p2, p3);
                __half2 h01 = *reinterpret_cast<__half2*>(&hp01);
                __half2 h23 = *reinterpret_cast<__half2*>(&hp23);
                uint32_t lp01 = pack2h(p0 - __low2float(h01), p1 - __high2float(h01));
                uint32_t lp23 = pack2h(p2 - __low2float(h23), p3 - __high2float(h23));
                int kc = t >> 1, hf = (t & 1) * 2;
                ph[kc][hf]     = hp01;  ph[kc][hf + 1] = hp23;
                pl[kc][hf]     = lp01;  pl[kc][hf + 1] = lp23;
            }
            ps0 += __shfl_xor_sync(0xFFFFFFFFu, ps0, 1);
            ps0 += __shfl_xor_sync(0xFFFFFFFFu, ps0, 2);
            ps1 += __shfl_xor_sync(0xFFFFFFFFu, ps1, 1);
            ps1 += __shfl_xor_sync(0xFFFFFFFFu, ps1, 2);
            l0 += ps0; l1 += ps1;

            // ---------- PV: O += (Phi + Plo) * Vhi
            #pragma unroll
            for (int kc = 0; kc < 4; kc++) {
                #pragma unroll
                for (int g = 0; g < 4; g++) {
                    uint32_t vh[4];
                    uint32_t addr = sbase + VOFF
                        + (kc * 16 + (lane & 7) + ((lane >> 3) & 1) * 8) * AT_STRB
                        + (g * 16 + ((lane >> 4) & 1) * 8) * 2;
                    ldsm4t(vh[0], vh[1], vh[2], vh[3], addr);
                    uint32_t bh0[2] = {vh[0], vh[1]};
                    uint32_t bh1[2] = {vh[2], vh[3]};
                    mma16816(ctxa[2*g],   ph[kc], bh0);
                    mma16816(ctxa[2*g],   pl[kc], bh0);
                    mma16816(ctxa[2*g+1], ph[kc], bh1);
                    mma16816(ctxa[2*g+1], pl[kc], bh1);
                }
            }
        }
    }

    float il0 = 1.f / l0, il1 = 1.f / l1;
    const int rtop = qrow0 + wm + (lane >> 2);
    float* c0p = ctx + ((size_t)(b * S_LEN) + rtop) * D_MODEL + h * HDIM;
    float* c1p = c0p + 8 * (size_t)D_MODEL;
    #pragma unroll
    for (int t = 0; t < 8; t++) {
        int col = t * 8 + (lane & 3) * 2;
        c0p[col]     = ctxa[t][0] * il0;
        c0p[col + 1] = ctxa[t][1] * il0;
        c1p[col]     = ctxa[t][2] * il1;
        c1p[col + 1] = ctxa[t][3] * il1;
    }
}

// ---------------- host launch -------------------------------------------------
extern "C" void kernel_launch(void* const* d_in, const int* in_sizes, int n_in,
                              void* d_out, int out_size)
{
    const float* x  = (const float*)d_in[0];
    const float* Wq = (const float*)d_in[1];
    const float* Wk = (const float*)d_in[2];
    const float* Wv = (const float*)d_in[3];
    const float* Wo = (const float*)d_in[4];
    float* out = (float*)d_out;

    float *q, *k, *v, *ctx;
    __half *ahat, *wq, *wk, *wv, *wo, *qhi, *qlo, *khi, *vhi;
    cudaGetSymbolAddress((void**)&q,    g_q);
    cudaGetSymbolAddress((void**)&k,    g_k);
    cudaGetSymbolAddress((void**)&v,    g_v);
    cudaGetSymbolAddress((void**)&ctx,  g_ctx);
    cudaGetSymbolAddress((void**)&ahat, g_ahat);
    cudaGetSymbolAddress((void**)&wq,   g_wq);
    cudaGetSymbolAddress((void**)&wk,   g_wk);
    cudaGetSymbolAddress((void**)&wv,   g_wv);
    cudaGetSymbolAddress((void**)&wo,   g_wo);
    cudaGetSymbolAddress((void**)&qhi,  g_qhi);
    cudaGetSymbolAddress((void**)&qlo,  g_qlo);
    cudaGetSymbolAddress((void**)&khi,  g_khi);
    cudaGetSymbolAddress((void**)&vhi,  g_vhi);

    static int smem_set = 0;
    if (!smem_set) {
        cudaFuncSetAttribute(gemm_hmma, cudaFuncAttributeMaxDynamicSharedMemorySize, GSMEM);
        smem_set = 1;
    }

    // conversions
    {
        int total = MROWS * KDIM;
        conv_split<<<(total + 255) / 256, 256>>>(x, ahat, total);
        dim3 blk(32, 32);
        conv_wt<<<dim3(D_MODEL / 32, KDIM / 32), blk>>>(Wq, wq, D_MODEL);
        conv_wt<<<dim3(KVD / 32,     KDIM / 32), blk>>>(Wk, wk, KVD);
        conv_wt<<<dim3(KVD / 32,     KDIM / 32), blk>>>(Wv, wv, KVD);
        conv_wt<<<dim3(D_MODEL / 32, KDIM / 32), blk>>>(Wo, wo, D_MODEL);
        rope_table<<<(S_LEN * 32 + 255) / 256, 256>>>();
    }

    // QKV projections
    gemm_hmma<<<dim3(D_MODEL / BN, MROWS / BM), 256, GSMEM>>>(ahat, wq, q, D_MODEL);
    gemm_hmma<<<dim3(KVD / BN,     MROWS / BM), 256, GSMEM>>>(ahat, wk, k, KVD);
    gemm_hmma<<<dim3(KVD / BN,     MROWS / BM), 256, GSMEM>>>(ahat, wv, v, KVD);

    // RoPE + fp16 conversion
    {
        int pairs_q = MROWS * NHEADS * 32;
        int pairs_k = MROWS * NKVH  * 32;
        rope_split_q<<<(pairs_q + 255) / 256, 256>>>(q, qhi, qlo, pairs_q);
        rope_half_k<<<(pairs_k + 255) / 256, 256>>>(k, khi, pairs_k);
        int tv = MROWS * KVD;
        v_half<<<(tv + 255) / 256, 256>>>(v, vhi, tv);
    }

    // attention
    attn_hmma<<<dim3(S_LEN / 128, NHEADS, BATCH), 256>>>(qhi, qlo, khi, vhi, ctx);

    // output projection
    {
        int total = MROWS * KDIM;
        conv_split<<<(total + 255) / 256, 256>>>(ctx, ahat, total);
        gemm_hmma<<<dim3(D_MODEL / BN, MROWS / BM), 256, GSMEM>>>(ahat, wo, out, D_MODEL);
    }
}